// round 12
// baseline (speedup 1.0000x reference)
#include <cuda_runtime.h>
#include <cuda_fp16.h>
#include <cstdint>

// Problem constants (fixed-shape problem)
#define MAXN 50000
#define KDEG 16

#define KHW   72     // W / h / xp row stride in halves (64 + 8 pad) -> conflict-free
#define XGS   264    // s_xg row stride in halves (256 + 8 pad)
#define KH128 136    // epilogue [x||h] row stride in halves
#define WS128 68     // word stride of KH128

// ---------------- scratch (device globals: allocation-free) ----------------
__device__ __half g_xp [MAXN * 64];     // projected feats, fp16
__device__ __half g_xg [MAXN * 256];    // precomputed Wx*xp + b, permuted cols, fp16
__device__ float  g_h1 [MAXN * 64];
__device__ float  g_h2 [MAXN * 128];
__device__ float  g_t1 [MAXN * 192];
__device__ float  g_t2 [MAXN * 64];

__device__ __half g_wx1 [256 * 64];     // permuted Wx [pcol][k]
__device__ __half g_wh1 [256 * 64];     // permuted Wh [pcol][k]
__device__ __half g_wx2 [256 * 64];
__device__ __half g_wh2 [256 * 64];
__device__ float  g_bs1 [256];          // permuted bih+bhh
__device__ float  g_bs2 [256];
__device__ __half g_wo1h[64 * 128],  g_wo1l[64 * 128];
__device__ __half g_wo2h[128 * 128], g_wo2l[128 * 128];
__device__ __half g_pT1h[64 * 64],   g_pT1l[64 * 64];
__device__ __half g_pT2h[64 * 64],   g_pT2l[64 * 64];
__device__ __half g_l1h [192 * 128], g_l1l [192 * 128];
__device__ __half g_l2h [64 * 192],  g_l2l [64 * 192];
__device__ __half g_l3h [64 * 64],   g_l3l [64 * 64];

// ---------------- helpers ----------------
__device__ __forceinline__ __half2 tanh2(__half2 x) {
    __half2 y;
    asm("tanh.approx.f16x2 %0, %1;" : "=r"(*(uint32_t*)&y) : "r"(*(const uint32_t*)&x));
    return y;
}
__device__ __forceinline__ __half2 sig2(__half2 x) {
    const __half2 h05 = __float2half2_rn(0.5f);
    return __hfma2(tanh2(__hmul2(x, h05)), h05, h05);
}

#define MMA_F16(D, A, b0, b1)                                                   \
    asm volatile("mma.sync.aligned.m16n8k16.row.col.f32.f16.f16.f32 "           \
                 "{%0,%1,%2,%3}, {%4,%5,%6,%7}, {%8,%9}, {%0,%1,%2,%3};"        \
                 : "+f"(D[0]), "+f"(D[1]), "+f"(D[2]), "+f"(D[3])               \
                 : "r"(A[0]), "r"(A[1]), "r"(A[2]), "r"(A[3]), "r"(b0), "r"(b1));

#define LDSM_X4(R, addr)                                                        \
    asm volatile("ldmatrix.sync.aligned.m8n8.x4.shared.b16 {%0,%1,%2,%3}, [%4];"\
                 : "=r"((R)[0]), "=r"((R)[1]), "=r"((R)[2]), "=r"((R)[3])       \
                 : "r"(addr));

// Gate-column permutation: each thread's accumulator fragment owns the full
// (i,f,g,o) quadruple for its hidden units.
__device__ __forceinline__ int perm_orig_col(int p) {
    int nj = p >> 6, rr = p & 63;
    int tp = rr >> 4, r2 = rr & 15;
    int half_ = r2 >> 3, r3 = r2 & 7;
    int q = r3 >> 1, low = r3 & 1;
    int gate = half_ * 2 + low;             // 0=i 1=f 2=g 3=o
    int jg = nj * 16 + q * 4 + tp;
    return gate * 64 + jg;
}

__device__ __forceinline__ void wsplit(__half* hi, __half* lo, int idx, float v) {
    __half h = __float2half_rn(v);
    hi[idx] = h;
    lo[idx] = __float2half_rn(v - __half2float(h));
}

// ---------------- single fused prep kernel ----------------
__global__ void k_prep_all(
    const float* p1wih, const float* p1whh, const float* p1bih, const float* p1bhh,
    const float* p2wih, const float* p2whh, const float* p2bih, const float* p2bhh,
    const float* p1llw, const float* p1lrw, const float* p2llw, const float* p2lrw,
    const float* p1pw, const float* p2pw,
    const float* l1w, const float* l2w, const float* l3w) {
    int b = blockIdx.x, t = threadIdx.x;
    if (b < 64) {                        // wx1: 256x64
        int idx = b * 256 + t;
        int p = idx >> 6, k = idx & 63;
        g_wx1[idx] = __float2half_rn(p1wih[perm_orig_col(p) * 64 + k]);
        if (idx < 256) { int g2 = perm_orig_col(idx); g_bs1[idx] = p1bih[g2] + p1bhh[g2]; }
    } else if (b < 128) {                // wh1
        int idx = (b - 64) * 256 + t;
        int p = idx >> 6, k = idx & 63;
        g_wh1[idx] = __float2half_rn(p1whh[perm_orig_col(p) * 64 + k]);
    } else if (b < 192) {                // wx2
        int idx = (b - 128) * 256 + t;
        int p = idx >> 6, k = idx & 63;
        g_wx2[idx] = __float2half_rn(p2wih[perm_orig_col(p) * 64 + k]);
        if (idx < 256) { int g2 = perm_orig_col(idx); g_bs2[idx] = p2bih[g2] + p2bhh[g2]; }
    } else if (b < 256) {                // wh2
        int idx = (b - 192) * 256 + t;
        int p = idx >> 6, k = idx & 63;
        g_wh2[idx] = __float2half_rn(p2whh[perm_orig_col(p) * 64 + k]);
    } else if (b < 288) {                // wo1: 64x128
        int idx = (b - 256) * 256 + t;
        int o = idx >> 7, k = idx & 127;
        wsplit(g_wo1h, g_wo1l, idx, k < 64 ? p1lrw[o * 64 + k] : p1llw[o * 64 + (k - 64)]);
    } else if (b < 352) {                // wo2: 128x128
        int idx = (b - 288) * 256 + t;
        int o = idx >> 7, k = idx & 127;
        wsplit(g_wo2h, g_wo2l, idx, k < 64 ? p2lrw[o * 64 + k] : p2llw[o * 64 + (k - 64)]);
    } else if (b < 368) {                // pT1
        int idx = (b - 352) * 256 + t;
        wsplit(g_pT1h, g_pT1l, idx, p1pw[idx]);
    } else if (b < 384) {                // pT2
        int idx = (b - 368) * 256 + t;
        wsplit(g_pT2h, g_pT2l, idx, p2pw[idx]);
    } else if (b < 480) {                // l1
        int idx = (b - 384) * 256 + t;
        wsplit(g_l1h, g_l1l, idx, l1w[idx]);
    } else if (b < 528) {                // l2
        int idx = (b - 480) * 256 + t;
        wsplit(g_l2h, g_l2l, idx, l2w[idx]);
    } else {                             // l3
        int idx = (b - 528) * 256 + t;
        wsplit(g_l3h, g_l3l, idx, l3w[idx]);
    }
}

__global__ void k_edge_copy(const int* __restrict__ ei, float* __restrict__ out, int count) {
    int i = blockIdx.x * blockDim.x + threadIdx.x;
    if (i < count) out[i] = (float)ei[i];
}

// ---------------- xg precompute: xg[n][p] = Wx(perm)·xp[n] + b, fp16 ----------------
// 64 nodes/block, 256 threads, warp grid 2(m32) x 4(n64), K=64.
__global__ __launch_bounds__(256, 2)
void xg_kernel(const __half* __restrict__ xp, const __half* __restrict__ wx,
               const float* __restrict__ bs, __half* __restrict__ xg, int N) {
    extern __shared__ __half sh[];
    __half* s_w = sh;                    // 256*KHW
    __half* s_a = s_w + 256 * KHW;       // 64*KHW
    float*  s_b = (float*)(s_a + 64 * KHW);

    const int tx = threadIdx.x, base = blockIdx.x * 64;
    const int lane = tx & 31, w = tx >> 5;
    const int mg = w >> 2, nj = w & 3;
    const int nwb = nj * 64, mrow = mg * 32;
    const int r = lane >> 2, q = lane & 3;
    const int tile = lane >> 3, lrow = lane & 7;

    for (int i = tx; i < 2048; i += 256) {              // 256 rows * 8 uint4
        int row = i >> 3, c = i & 7;
        ((uint4*)(s_w + row * KHW))[c] = ((const uint4*)wx)[i];
    }
    s_b[tx] = bs[tx];
    for (int i = tx; i < 512; i += 256) {               // 64 rows * 8 uint4
        int row = i >> 3, c = i & 7;
        int node = base + row;
        uint4 v = make_uint4(0u, 0u, 0u, 0u);
        if (node < N) v = ((const uint4*)(xp + (size_t)node * 64))[c];
        ((uint4*)(s_a + row * KHW))[c] = v;
    }
    __syncthreads();

    const uint32_t s_a_u = (uint32_t)__cvta_generic_to_shared(s_a);
    const uint32_t s_w_u = (uint32_t)__cvta_generic_to_shared(s_w);
    uint32_t aaddr[2], baddr[4];
    #pragma unroll
    for (int mt = 0; mt < 2; mt++)
        aaddr[mt] = s_a_u + 2 * ((mrow + mt * 16 + (tile & 1) * 8 + lrow) * KHW + (tile >> 1) * 8);
    #pragma unroll
    for (int np = 0; np < 4; np++)
        baddr[np] = s_w_u + 2 * ((nwb + np * 16 + (tile >> 1) * 8 + lrow) * KHW + (tile & 1) * 8);

    float acc[2][8][4];
    #pragma unroll
    for (int mt = 0; mt < 2; mt++)
        #pragma unroll
        for (int nt = 0; nt < 8; nt++) {
            float b0 = s_b[nwb + nt * 8 + 2 * q], b1 = s_b[nwb + nt * 8 + 2 * q + 1];
            acc[mt][nt][0] = b0; acc[mt][nt][1] = b1;
            acc[mt][nt][2] = b0; acc[mt][nt][3] = b1;
        }
    #pragma unroll
    for (int kc = 0; kc < 4; kc++) {
        const uint32_t ko = kc * 32;
        uint32_t af[2][4];
        LDSM_X4(af[0], aaddr[0] + ko);
        LDSM_X4(af[1], aaddr[1] + ko);
        #pragma unroll
        for (int np = 0; np < 4; np++) {
            uint32_t bf[4];
            LDSM_X4(bf, baddr[np] + ko);
            MMA_F16(acc[0][2 * np],     af[0], bf[0], bf[1]);
            MMA_F16(acc[1][2 * np],     af[1], bf[0], bf[1]);
            MMA_F16(acc[0][2 * np + 1], af[0], bf[2], bf[3]);
            MMA_F16(acc[1][2 * np + 1], af[1], bf[2], bf[3]);
        }
    }
    #pragma unroll
    for (int mt = 0; mt < 2; mt++)
        #pragma unroll
        for (int rr = 0; rr < 2; rr++) {
            int node = base + mrow + mt * 16 + r + 8 * rr;
            if (node < N) {
                #pragma unroll
                for (int nt = 0; nt < 8; nt++) {
                    int c0 = nwb + nt * 8 + 2 * q;
                    *(__half2*)(xg + (size_t)node * 256 + c0) =
                        __floats2half2_rn(acc[mt][nt][rr * 2 + 0], acc[mt][nt][rr * 2 + 1]);
                }
            }
        }
}

// ---------------- fused LSTM-SAGE kernel (K=64 recurrence, 2 CTA/SM) ----------------
// Block = 64 nodes, 256 threads = 8 warps, warp grid 2(m32) x 4(n64).
// Gate accumulators initialized from gathered xg (x-part precomputed).
// smem arena (halves): phase A: [wh 0..18432) [h 18432..23040) [xg 23040..39936)
//                      phase B: [woh 0..17408) [wol ..34816) [ih ..43520) [il ..52224)
// tail: ob(256f) + src(1024i). Last-step h written directly into ih plane.
template<int OUT>
__global__ __launch_bounds__(256, 2)
void lstm_mma_kernel(const __half* __restrict__ xg,
                     const float*  __restrict__ xin,
                     const int*    __restrict__ src,
                     const __half* __restrict__ whc,    // [256][64] permuted
                     const __half* __restrict__ wohi,   // [OUT][128]
                     const __half* __restrict__ wolo,
                     const float*  __restrict__ ob,
                     float* __restrict__ out,
                     int N) {
    extern __shared__ __half smh[];
    __half* s_wh  = smh;                     // phase A
    __half* s_h   = smh + 18432;
    __half* s_xg  = smh + 23040;
    __half* s_woh = smh;                     // phase B
    __half* s_wol = smh + 17408;
    __half* s_ih  = smh + 34816;
    __half* s_il  = smh + 43520;
    float*  s_ob  = (float*)(smh + 52224);
    int*    s_src = (int*)(s_ob + 256);

    const int tx = threadIdx.x;
    const int base = blockIdx.x * 64;
    const int lane = tx & 31, w = tx >> 5;
    const int mg = w >> 2, nj = w & 3;
    const int nwb = nj * 64;
    const int mrow = mg * 32;
    const int r = lane >> 2, q = lane & 3;
    const int tile = lane >> 3, lrow = lane & 7;

    // Wh -> smem [p][k]
    for (int i = tx; i < 2048; i += 256) {               // 256 rows * 8 uint4
        int row = i >> 3, c = i & 7;
        ((uint4*)(s_wh + row * KHW))[c] = ((const uint4*)whc)[i];
    }
    for (int i = tx; i < 1024; i += 256) {
        int node = base + (i >> 4);
        s_src[i] = (node < N) ? src[node * KDEG + (i & 15)] : 0;
    }
    // zero h and the epilogue lo plane (h cols of il stay zero)
    for (int i = tx; i < (64 * KHW) / 8; i += 256)
        ((uint4*)s_h)[i] = make_uint4(0u, 0u, 0u, 0u);
    for (int i = tx; i < (64 * KH128) / 8; i += 256)
        ((uint4*)s_il)[i] = make_uint4(0u, 0u, 0u, 0u);
    __syncthreads();

    float cst[2][4][2];
    #pragma unroll
    for (int a = 0; a < 2; a++)
        #pragma unroll
        for (int bb = 0; bb < 4; bb++) { cst[a][bb][0] = 0.f; cst[a][bb][1] = 0.f; }

    const uint32_t s_h_u  = (uint32_t)__cvta_generic_to_shared(s_h);
    const uint32_t s_wh_u = (uint32_t)__cvta_generic_to_shared(s_wh);
    uint32_t aaddr[2], baddr[4];
    #pragma unroll
    for (int mt = 0; mt < 2; mt++)
        aaddr[mt] = s_h_u + 2 * ((mrow + mt * 16 + (tile & 1) * 8 + lrow) * KHW + (tile >> 1) * 8);
    #pragma unroll
    for (int np = 0; np < 4; np++)
        baddr[np] = s_wh_u + 2 * ((nwb + np * 16 + (tile >> 1) * 8 + lrow) * KHW + (tile & 1) * 8);

    // gather xg[src[n,t]] (512B per node) into s_xg
    auto gather = [&](int t) {
        #pragma unroll
        for (int i = 0; i < 8; i++) {
            int idx = tx + i * 256;                      // 2048 = 64 rows * 32 uint4
            int n = idx >> 5, c = idx & 31;
            uint4 v = *(const uint4*)(xg + (size_t)s_src[n * KDEG + t] * 256 + c * 8);
            *(uint4*)(s_xg + n * XGS + c * 8) = v;
        }
    };

    gather(0);

    for (int t = 0; t < KDEG; t++) {
        __syncthreads();   // gather + h writes visible

        // acc init = gathered x-part (includes bias)
        float acc[2][8][4];
        #pragma unroll
        for (int mt = 0; mt < 2; mt++)
            #pragma unroll
            for (int rr = 0; rr < 2; rr++) {
                int row = mrow + mt * 16 + r + 8 * rr;
                const uint32_t* xr = (const uint32_t*)(s_xg + row * XGS) + (nwb >> 1) + q;
                #pragma unroll
                for (int nt = 0; nt < 8; nt++) {
                    uint32_t u = xr[nt * 4];
                    float2 f = __half22float2(*(__half2*)&u);
                    acc[mt][nt][rr * 2 + 0] = f.x;
                    acc[mt][nt][rr * 2 + 1] = f.y;
                }
            }

        // recurrent GEMM: += h_{t-1} @ Wh^T   (K = 64)
        #pragma unroll
        for (int kc = 0; kc < 4; kc++) {
            const uint32_t ko = kc * 32;
            uint32_t af[2][4];
            LDSM_X4(af[0], aaddr[0] + ko);
            LDSM_X4(af[1], aaddr[1] + ko);
            #pragma unroll
            for (int np = 0; np < 4; np++) {
                uint32_t bf[4];
                LDSM_X4(bf, baddr[np] + ko);
                MMA_F16(acc[0][2 * np],     af[0], bf[0], bf[1]);
                MMA_F16(acc[1][2 * np],     af[1], bf[0], bf[1]);
                MMA_F16(acc[0][2 * np + 1], af[0], bf[2], bf[3]);
                MMA_F16(acc[1][2 * np + 1], af[1], bf[2], bf[3]);
            }
        }
        __syncthreads();   // s_h / s_xg reads done

        // activation: f16x2 tanh path, c-state fp32
        const bool last = (t == KDEG - 1);
        #pragma unroll
        for (int mt = 0; mt < 2; mt++) {
            #pragma unroll
            for (int rr = 0; rr < 2; rr++) {
                int row = mrow + mt * 16 + r + 8 * rr;
                __half2* dst = last
                    ? (__half2*)(s_ih + row * KH128 + 64 + nj * 16 + q * 4)
                    : (__half2*)(s_h  + row * KHW  +      nj * 16 + q * 4);
                #pragma unroll
                for (int p = 0; p < 2; p++) {
                    int t0 = 2 * p, t1 = 2 * p + 1;
                    __half2 i2 = __floats2half2_rn(acc[mt][2 * t0][rr * 2 + 0], acc[mt][2 * t1][rr * 2 + 0]);
                    __half2 f2 = __floats2half2_rn(acc[mt][2 * t0][rr * 2 + 1], acc[mt][2 * t1][rr * 2 + 1]);
                    __half2 g2 = __floats2half2_rn(acc[mt][2 * t0 + 1][rr * 2 + 0], acc[mt][2 * t1 + 1][rr * 2 + 0]);
                    __half2 o2 = __floats2half2_rn(acc[mt][2 * t0 + 1][rr * 2 + 1], acc[mt][2 * t1 + 1][rr * 2 + 1]);
                    __half2 si = sig2(i2), sf = sig2(f2), so = sig2(o2), tg = tanh2(g2);
                    float2 fi = __half22float2(si), ff = __half22float2(sf), fg = __half22float2(tg);
                    float c0 = ff.x * cst[mt][t0][rr] + fi.x * fg.x;
                    float c1 = ff.y * cst[mt][t1][rr] + fi.y * fg.y;
                    cst[mt][t0][rr] = c0; cst[mt][t1][rr] = c1;
                    __half2 tc = tanh2(__floats2half2_rn(c0, c1));
                    dst[p] = __hmul2(so, tc);
                }
            }
        }
        if (t + 1 < KDEG) gather(t + 1);
    }
    __syncthreads();   // phase A fully consumed

    // ---- fused SAGE output, split fp16: out = relu([x||h]*Wo^T + ob) ----
    constexpr int NT2 = OUT / 32;
    const int nwb2 = nj * (OUT / 4);

    for (int i = tx; i < OUT * 16; i += 256) {           // OUT rows * 16 uint4
        int row = i >> 4, c = i & 15;
        ((uint4*)(s_woh + row * KH128))[c] = ((const uint4*)wohi)[i];
        ((uint4*)(s_wol + row * KH128))[c] = ((const uint4*)wolo)[i];
    }
    for (int i = tx; i < OUT; i += 256) s_ob[i] = ob[i];
    #pragma unroll
    for (int i = 0; i < 4; i++) {
        int idx = tx + i * 256;                          // 64 rows * 16 float4
        int n = idx >> 4, c = idx & 15;
        int node = base + n;
        float4 v = make_float4(0.f, 0.f, 0.f, 0.f);
        if (node < N) v = ((const float4*)(xin + (size_t)node * 64))[c];
        __half2 h0 = __floats2half2_rn(v.x, v.y), h1 = __floats2half2_rn(v.z, v.w);
        float2 f0 = __half22float2(h0), f1 = __half22float2(h1);
        __half2* dh = (__half2*)(s_ih + n * KH128 + c * 4);
        __half2* dl = (__half2*)(s_il + n * KH128 + c * 4);
        dh[0] = h0; dh[1] = h1;
        dl[0] = __floats2half2_rn(v.x - f0.x, v.y - f0.y);
        dl[1] = __floats2half2_rn(v.z - f1.x, v.w - f1.y);
    }
    __syncthreads();

    float a2[2][NT2][4];
    #pragma unroll
    for (int mt = 0; mt < 2; mt++)
        #pragma unroll
        for (int nt = 0; nt < NT2; nt++) {
            int c0 = nwb2 + nt * 8 + 2 * q;
            a2[mt][nt][0] = s_ob[c0];     a2[mt][nt][1] = s_ob[c0 + 1];
            a2[mt][nt][2] = s_ob[c0];     a2[mt][nt][3] = s_ob[c0 + 1];
        }
    #pragma unroll 2
    for (int kc = 0; kc < 8; kc++) {
        const int kw = kc * 8;
        uint32_t ah[2][4], al[2][4];
        #pragma unroll
        for (int mt = 0; mt < 2; mt++) {
            const uint32_t* ap = (const uint32_t*)s_ih + (mrow + mt * 16 + r) * WS128 + kw + q;
            const uint32_t* lp = (const uint32_t*)s_il + (mrow + mt * 16 + r) * WS128 + kw + q;
            ah[mt][0] = ap[0]; ah[mt][1] = ap[8 * WS128]; ah[mt][2] = ap[4]; ah[mt][3] = ap[8 * WS128 + 4];
            al[mt][0] = lp[0]; al[mt][1] = lp[8 * WS128]; al[mt][2] = lp[4]; al[mt][3] = lp[8 * WS128 + 4];
        }
        #pragma unroll
        for (int nt = 0; nt < NT2; nt++) {
            const uint32_t* bh = (const uint32_t*)s_woh + (nwb2 + nt * 8 + r) * WS128 + kw + q;
            const uint32_t* bl = (const uint32_t*)s_wol + (nwb2 + nt * 8 + r) * WS128 + kw + q;
            uint32_t bh0 = bh[0], bh1 = bh[4], bl0 = bl[0], bl1 = bl[4];
            #pragma unroll
            for (int mt = 0; mt < 2; mt++) {
                MMA_F16(a2[mt][nt], ah[mt], bh0, bh1);
                MMA_F16(a2[mt][nt], ah[mt], bl0, bl1);
                MMA_F16(a2[mt][nt], al[mt], bh0, bh1);
            }
        }
    }
    #pragma unroll
    for (int mt = 0; mt < 2; mt++)
        #pragma unroll
        for (int nt = 0; nt < NT2; nt++)
            #pragma unroll
            for (int rr = 0; rr < 2; rr++) {
                int node = base + mrow + mt * 16 + r + 8 * rr;
                if (node < N) {
                    int c0 = nwb2 + nt * 8 + 2 * q;
                    float2 v;
                    v.x = fmaxf(a2[mt][nt][2 * rr + 0], 0.f);
                    v.y = fmaxf(a2[mt][nt][2 * rr + 1], 0.f);
                    *(float2*)(out + (size_t)node * OUT + c0) = v;
                }
            }
}

// ---------------- split-fp16 MMA linear + relu ----------------
template<int KIN, int KOUT, bool HOUT>
__global__ __launch_bounds__(256, 1)
void mma_linear(const float* __restrict__ A,
                const __half* __restrict__ Whi, const __half* __restrict__ Wlo,
                const float* __restrict__ bias, void* __restrict__ outp, int N) {
    constexpr int KH = KIN + 8, WSL = KH / 2, CH = KIN / 16;
    constexpr int NT = KOUT / 32;
    extern __shared__ __half sh[];
    __half* s_wh = sh;
    __half* s_wl = s_wh + KOUT * KH;
    __half* s_ah = s_wl + KOUT * KH;
    __half* s_al = s_ah + 128 * KH;
    float*  s_b  = (float*)(s_al + 128 * KH);

    const int tx = threadIdx.x, base = blockIdx.x * 128;
    const int lane = tx & 31, w = tx >> 5;
    const int mg = w >> 2, nj = w & 3;
    const int r = lane >> 2, q = lane & 3;
    const int mrow = mg * 64, nwb = nj * (KOUT / 4);

    for (int i = tx; i < KOUT * (KIN / 8); i += 256) {
        int row = i / (KIN / 8), c = i % (KIN / 8);
        ((uint4*)(s_wh + row * KH))[c] = ((const uint4*)Whi)[i];
        ((uint4*)(s_wl + row * KH))[c] = ((const uint4*)Wlo)[i];
    }
    for (int i = tx; i < KOUT; i += 256) s_b[i] = bias[i];
    for (int i = tx; i < 128 * (KIN / 4); i += 256) {
        int n = i / (KIN / 4), c = i % (KIN / 4);
        int node = base + n;
        float4 v = make_float4(0.f, 0.f, 0.f, 0.f);
        if (node < N) v = ((const float4*)(A + (size_t)node * KIN))[c];
        __half2 h0 = __floats2half2_rn(v.x, v.y), h1 = __floats2half2_rn(v.z, v.w);
        float2 f0 = __half22float2(h0), f1 = __half22float2(h1);
        __half2* dh = (__half2*)(s_ah + n * KH + c * 4);
        __half2* dl = (__half2*)(s_al + n * KH + c * 4);
        dh[0] = h0; dh[1] = h1;
        dl[0] = __floats2half2_rn(v.x - f0.x, v.y - f0.y);
        dl[1] = __floats2half2_rn(v.z - f1.x, v.w - f1.y);
    }
    __syncthreads();

    float acc[4][NT][4];
    #pragma unroll
    for (int mt = 0; mt < 4; mt++)
        #pragma unroll
        for (int nt = 0; nt < NT; nt++) {
            int c0 = nwb + nt * 8 + 2 * q;
            acc[mt][nt][0] = s_b[c0];     acc[mt][nt][1] = s_b[c0 + 1];
            acc[mt][nt][2] = s_b[c0];     acc[mt][nt][3] = s_b[c0 + 1];
        }
    #pragma unroll 2
    for (int kc = 0; kc < CH; kc++) {
        const int kw = kc * 8;
        uint32_t ah[4][4], al[4][4];
        #pragma unroll
        for (int mt = 0; mt < 4; mt++) {
            const uint32_t* ap = (const uint32_t*)s_ah + (mrow + mt * 16 + r) * WSL + kw + q;
            const uint32_t* lp = (const uint32_t*)s_al + (mrow + mt * 16 + r) * WSL + kw + q;
            ah[mt][0] = ap[0]; ah[mt][1] = ap[8 * WSL]; ah[mt][2] = ap[4]; ah[mt][3] = ap[8 * WSL + 4];
            al[mt][0] = lp[0]; al[mt][1] = lp[8 * WSL]; al[mt][2] = lp[4]; al[mt][3] = lp[8 * WSL + 4];
        }
        #pragma unroll
        for (int nt = 0; nt < NT; nt++) {
            const uint32_t* bh = (const uint32_t*)s_wh + (nwb + nt * 8 + r) * WSL + kw + q;
            const uint32_t* bl = (const uint32_t*)s_wl + (nwb + nt * 8 + r) * WSL + kw + q;
            uint32_t bh0 = bh[0], bh1 = bh[4], bl0 = bl[0], bl1 = bl[4];
            #pragma unroll
            for (int mt = 0; mt < 4; mt++) {
                MMA_F16(acc[mt][nt], ah[mt], bh0, bh1);
                MMA_F16(acc[mt][nt], ah[mt], bl0, bl1);
                MMA_F16(acc[mt][nt], al[mt], bh0, bh1);
            }
        }
    }
    #pragma unroll
    for (int mt = 0; mt < 4; mt++)
        #pragma unroll
        for (int nt = 0; nt < NT; nt++)
            #pragma unroll
            for (int rr = 0; rr < 2; rr++) {
                int node = base + mrow + mt * 16 + r + 8 * rr;
                if (node < N) {
                    int c0 = nwb + nt * 8 + 2 * q;
                    float vx = fmaxf(acc[mt][nt][2 * rr + 0], 0.f);
                    float vy = fmaxf(acc[mt][nt][2 * rr + 1], 0.f);
                    if (HOUT) {
                        *(__half2*)((__half*)outp + (size_t)node * KOUT + c0) =
                            __floats2half2_rn(vx, vy);
                    } else {
                        *(float2*)((float*)outp + (size_t)node * KOUT + c0) =
                            make_float2(vx, vy);
                    }
                }
            }
}

// ---------------- host launcher ----------------
static void* symaddr(const void* sym) {
    void* p = nullptr;
    cudaGetSymbolAddress(&p, sym);
    return p;
}

extern "C" void kernel_launch(void* const* d_in, const int* in_sizes, int n_in,
                              void* d_out, int out_size) {
    const float* x   = (const float*)d_in[0];
    const int*   ei  = (const int*)d_in[1];
    const int N = in_sizes[0] / 64;
    const int E = in_sizes[1] / 2;
    const int* src = ei;

    const float* p1pw  = (const float*)d_in[3];
    const float* p1pb  = (const float*)d_in[4];
    const float* p1wih = (const float*)d_in[5];
    const float* p1whh = (const float*)d_in[6];
    const float* p1bih = (const float*)d_in[7];
    const float* p1bhh = (const float*)d_in[8];
    const float* p1llw = (const float*)d_in[9];
    const float* p1llb = (const float*)d_in[10];
    const float* p1lrw = (const float*)d_in[11];
    const float* p2pw  = (const float*)d_in[12];
    const float* p2pb  = (const float*)d_in[13];
    const float* p2wih = (const float*)d_in[14];
    const float* p2whh = (const float*)d_in[15];
    const float* p2bih = (const float*)d_in[16];
    const float* p2bhh = (const float*)d_in[17];
    const float* p2llw = (const float*)d_in[18];
    const float* p2llb = (const float*)d_in[19];
    const float* p2lrw = (const float*)d_in[20];
    const float* l1w   = (const float*)d_in[21];
    const float* l1b   = (const float*)d_in[22];
    const float* l2w   = (const float*)d_in[23];
    const float* l2b   = (const float*)d_in[24];
    const float* l3w   = (const float*)d_in[25];
    const float* l3b   = (const float*)d_in[26];

    __half* xp  = (__half*)symaddr(g_xp);
    __half* xg  = (__half*)symaddr(g_xg);
    float*  h1  = (float*)symaddr(g_h1);
    float*  h2  = (float*)symaddr(g_h2);
    float*  t1  = (float*)symaddr(g_t1);
    float*  t2  = (float*)symaddr(g_t2);
    __half* wx1 = (__half*)symaddr(g_wx1);
    __half* wh1 = (__half*)symaddr(g_wh1);
    __half* wx2 = (__half*)symaddr(g_wx2);
    __half* wh2 = (__half*)symaddr(g_wh2);
    float*  bs1 = (float*)symaddr(g_bs1);
    float*  bs2 = (float*)symaddr(g_bs2);
    __half* wo1h = (__half*)symaddr(g_wo1h); __half* wo1l = (__half*)symaddr(g_wo1l);
    __half* wo2h = (__half*)symaddr(g_wo2h); __half* wo2l = (__half*)symaddr(g_wo2l);
    __half* pT1h = (__half*)symaddr(g_pT1h); __half* pT1l = (__half*)symaddr(g_pT1l);
    __half* pT2h = (__half*)symaddr(g_pT2h); __half* pT2l = (__half*)symaddr(g_pT2l);
    __half* l1h  = (__half*)symaddr(g_l1h);  __half* l1l  = (__half*)symaddr(g_l1l);
    __half* l2h  = (__half*)symaddr(g_l2h);  __half* l2l  = (__half*)symaddr(g_l2l);
    __half* l3h  = (__half*)symaddr(g_l3h);  __half* l3l  = (__half*)symaddr(g_l3l);

    // smem sizes
    const int SM_LSTM = 52224 * 2 + 256 * 4 + 1024 * 4;                          // 109568
    const int SM_XG   = (256 * KHW + 64 * KHW) * 2 + 256 * 4;                    // 47104
    const int SM_6464 = (2 * 64 * 72 + 2 * 128 * 72) * 2 + 64 * 4;               // 55552
    const int SM_L1   = (2 * 192 * 136 + 2 * 128 * 136) * 2 + 192 * 4;           // 174848
    const int SM_L2   = (2 * 64 * 200 + 2 * 128 * 200) * 2 + 64 * 4;             // 153856
    cudaFuncSetAttribute(lstm_mma_kernel<64>,        cudaFuncAttributeMaxDynamicSharedMemorySize, SM_LSTM);
    cudaFuncSetAttribute(lstm_mma_kernel<128>,       cudaFuncAttributeMaxDynamicSharedMemorySize, SM_LSTM);
    cudaFuncSetAttribute(xg_kernel,                  cudaFuncAttributeMaxDynamicSharedMemorySize, SM_XG);
    cudaFuncSetAttribute(mma_linear<64, 64, true>,   cudaFuncAttributeMaxDynamicSharedMemorySize, SM_6464);
    cudaFuncSetAttribute(mma_linear<64, 64, false>,  cudaFuncAttributeMaxDynamicSharedMemorySize, SM_6464);
    cudaFuncSetAttribute(mma_linear<128, 192, false>, cudaFuncAttributeMaxDynamicSharedMemorySize, SM_L1);
    cudaFuncSetAttribute(mma_linear<192, 64, false>, cudaFuncAttributeMaxDynamicSharedMemorySize, SM_L2);

    // --- fused weight prep ---
    k_prep_all<<<544, 256>>>(p1wih, p1whh, p1bih, p1bhh,
                             p2wih, p2whh, p2bih, p2bhh,
                             p1llw, p1lrw, p2llw, p2lrw,
                             p1pw, p2pw, l1w, l2w, l3w);

    const int NB128 = (N + 127) / 128;
    const int NB64  = (N + 63) / 64;

    // --- layer 1 ---
    mma_linear<64, 64, true><<<NB128, 256, SM_6464>>>(x, pT1h, pT1l, p1pb, xp, N);
    xg_kernel<<<NB64, 256, SM_XG>>>(xp, wx1, bs1, xg, N);
    lstm_mma_kernel<64><<<NB64, 256, SM_LSTM>>>(xg, x, src, wh1, wo1h, wo1l, p1llb, h1, N);
    // --- layer 2 ---
    mma_linear<64, 64, true><<<NB128, 256, SM_6464>>>(h1, pT2h, pT2l, p2pb, xp, N);
    xg_kernel<<<NB64, 256, SM_XG>>>(xp, wx2, bs2, xg, N);
    lstm_mma_kernel<128><<<NB64, 256, SM_LSTM>>>(xg, h1, src, wh2, wo2h, wo2l, p2llb, h2, N);
    // --- MLP head ---
    mma_linear<128, 192, false><<<NB128, 256, SM_L1>>>(h2, l1h, l1l, l1b, t1, N);
    mma_linear<192, 64, false><<<NB128, 256, SM_L2>>>(t1, l2h, l2l, l2b, t2, N);
    mma_linear<64, 64, false><<<NB128, 256, SM_6464>>>(t2, l3h, l3l, l3b, d_out, N);

    // --- edge_index passthrough if the output buffer holds it ---
    long hsz = (long)N * 64;
    if ((long)out_size > hsz) {
        long remaining = (long)out_size - hsz;
        int count = (int)((remaining < (long)2 * E) ? remaining : (long)2 * E);
        k_edge_copy<<<(count + 255) / 256, 256>>>(ei, (float*)d_out + hsz, count);
    }
}

// round 13
// speedup vs baseline: 1.2147x; 1.2147x over previous
#include <cuda_runtime.h>
#include <cuda_fp16.h>
#include <cstdint>

// Problem constants (fixed-shape problem)
#define MAXN 50000
#define KDEG 16

#define KHW   72     // W / h row stride in halves (64 + 8 pad) -> conflict-free
#define KH128 136    // epilogue [x||h] row stride in halves
#define WS128 68     // word stride of KH128

// ---------------- scratch (device globals: allocation-free) ----------------
__device__ __half g_xp [MAXN * 64];     // projected feats, fp16
__device__ __half g_xg [MAXN * 256];    // Wx*xp + b, fragment-ordered, fp16
__device__ float  g_h1 [MAXN * 64];
__device__ float  g_h2 [MAXN * 128];
__device__ float  g_t1 [MAXN * 192];
__device__ float  g_t2 [MAXN * 64];

__device__ __half g_wx1 [256 * 64];     // permuted Wx [pcol][k]
__device__ __half g_wh1 [256 * 64];     // permuted Wh [pcol][k]
__device__ __half g_wx2 [256 * 64];
__device__ __half g_wh2 [256 * 64];
__device__ float  g_bs1 [256];          // permuted bih+bhh
__device__ float  g_bs2 [256];
__device__ __half g_wo1h[64 * 128],  g_wo1l[64 * 128];
__device__ __half g_wo2h[128 * 128], g_wo2l[128 * 128];
__device__ __half g_pT1h[64 * 64],   g_pT1l[64 * 64];
__device__ __half g_pT2h[64 * 64],   g_pT2l[64 * 64];
__device__ __half g_l1h [192 * 128], g_l1l [192 * 128];
__device__ __half g_l2h [64 * 192],  g_l2l [64 * 192];
__device__ __half g_l3h [64 * 64],   g_l3l [64 * 64];

// ---------------- helpers ----------------
__device__ __forceinline__ __half2 tanh2(__half2 x) {
    __half2 y;
    asm("tanh.approx.f16x2 %0, %1;" : "=r"(*(uint32_t*)&y) : "r"(*(const uint32_t*)&x));
    return y;
}
__device__ __forceinline__ __half2 sig2(__half2 x) {
    const __half2 h05 = __float2half2_rn(0.5f);
    return __hfma2(tanh2(__hmul2(x, h05)), h05, h05);
}

#define MMA_F16(D, A, b0, b1)                                                   \
    asm volatile("mma.sync.aligned.m16n8k16.row.col.f32.f16.f16.f32 "           \
                 "{%0,%1,%2,%3}, {%4,%5,%6,%7}, {%8,%9}, {%0,%1,%2,%3};"        \
                 : "+f"(D[0]), "+f"(D[1]), "+f"(D[2]), "+f"(D[3])               \
                 : "r"(A[0]), "r"(A[1]), "r"(A[2]), "r"(A[3]), "r"(b0), "r"(b1));

#define LDSM_X4(R, addr)                                                        \
    asm volatile("ldmatrix.sync.aligned.m8n8.x4.shared.b16 {%0,%1,%2,%3}, [%4];"\
                 : "=r"((R)[0]), "=r"((R)[1]), "=r"((R)[2]), "=r"((R)[3])       \
                 : "r"(addr));

// Gate-column permutation: each thread's accumulator fragment owns the full
// (i,f,g,o) quadruple for its hidden units.
__device__ __forceinline__ int perm_orig_col(int p) {
    int nj = p >> 6, rr = p & 63;
    int tp = rr >> 4, r2 = rr & 15;
    int half_ = r2 >> 3, r3 = r2 & 7;
    int q = r3 >> 1, low = r3 & 1;
    int gate = half_ * 2 + low;             // 0=i 1=f 2=g 3=o
    int jg = nj * 16 + q * 4 + tp;
    return gate * 64 + jg;
}

__device__ __forceinline__ void wsplit(__half* hi, __half* lo, int idx, float v) {
    __half h = __float2half_rn(v);
    hi[idx] = h;
    lo[idx] = __float2half_rn(v - __half2float(h));
}

// ---------------- single fused prep kernel ----------------
__global__ void k_prep_all(
    const float* p1wih, const float* p1whh, const float* p1bih, const float* p1bhh,
    const float* p2wih, const float* p2whh, const float* p2bih, const float* p2bhh,
    const float* p1llw, const float* p1lrw, const float* p2llw, const float* p2lrw,
    const float* p1pw, const float* p2pw,
    const float* l1w, const float* l2w, const float* l3w) {
    int b = blockIdx.x, t = threadIdx.x;
    if (b < 64) {                        // wx1: 256x64
        int idx = b * 256 + t;
        int p = idx >> 6, k = idx & 63;
        g_wx1[idx] = __float2half_rn(p1wih[perm_orig_col(p) * 64 + k]);
        if (idx < 256) { int g2 = perm_orig_col(idx); g_bs1[idx] = p1bih[g2] + p1bhh[g2]; }
    } else if (b < 128) {                // wh1
        int idx = (b - 64) * 256 + t;
        int p = idx >> 6, k = idx & 63;
        g_wh1[idx] = __float2half_rn(p1whh[perm_orig_col(p) * 64 + k]);
    } else if (b < 192) {                // wx2
        int idx = (b - 128) * 256 + t;
        int p = idx >> 6, k = idx & 63;
        g_wx2[idx] = __float2half_rn(p2wih[perm_orig_col(p) * 64 + k]);
        if (idx < 256) { int g2 = perm_orig_col(idx); g_bs2[idx] = p2bih[g2] + p2bhh[g2]; }
    } else if (b < 256) {                // wh2
        int idx = (b - 192) * 256 + t;
        int p = idx >> 6, k = idx & 63;
        g_wh2[idx] = __float2half_rn(p2whh[perm_orig_col(p) * 64 + k]);
    } else if (b < 288) {                // wo1: 64x128
        int idx = (b - 256) * 256 + t;
        int o = idx >> 7, k = idx & 127;
        wsplit(g_wo1h, g_wo1l, idx, k < 64 ? p1lrw[o * 64 + k] : p1llw[o * 64 + (k - 64)]);
    } else if (b < 352) {                // wo2: 128x128
        int idx = (b - 288) * 256 + t;
        int o = idx >> 7, k = idx & 127;
        wsplit(g_wo2h, g_wo2l, idx, k < 64 ? p2lrw[o * 64 + k] : p2llw[o * 64 + (k - 64)]);
    } else if (b < 368) {                // pT1
        int idx = (b - 352) * 256 + t;
        wsplit(g_pT1h, g_pT1l, idx, p1pw[idx]);
    } else if (b < 384) {                // pT2
        int idx = (b - 368) * 256 + t;
        wsplit(g_pT2h, g_pT2l, idx, p2pw[idx]);
    } else if (b < 480) {                // l1
        int idx = (b - 384) * 256 + t;
        wsplit(g_l1h, g_l1l, idx, l1w[idx]);
    } else if (b < 528) {                // l2
        int idx = (b - 480) * 256 + t;
        wsplit(g_l2h, g_l2l, idx, l2w[idx]);
    } else {                             // l3
        int idx = (b - 528) * 256 + t;
        wsplit(g_l3h, g_l3l, idx, l3w[idx]);
    }
}

__global__ void k_edge_copy(const int* __restrict__ ei, float* __restrict__ out, int count) {
    int i = blockIdx.x * blockDim.x + threadIdx.x;
    if (i < count) out[i] = (float)ei[i];
}

// ---------------- xg precompute: xg[n] = Wx(perm)·xp[n] + b, fragment-ordered fp16 ----
// Output layout per node: pos = (nj*4 + q)*16 + nt*2 (+e) -> each consumer thread
// reads 32B contiguous; a warp reads 8 rows x 128B fully-sectored chunks.
__global__ __launch_bounds__(256, 2)
void xg_kernel(const __half* __restrict__ xp, const __half* __restrict__ wx,
               const float* __restrict__ bs, __half* __restrict__ xg, int N) {
    extern __shared__ __half sh[];
    __half* s_w = sh;                    // 256*KHW
    __half* s_a = s_w + 256 * KHW;       // 64*KHW
    float*  s_b = (float*)(s_a + 64 * KHW);

    const int tx = threadIdx.x, base = blockIdx.x * 64;
    const int lane = tx & 31, w = tx >> 5;
    const int mg = w >> 2, nj = w & 3;
    const int nwb = nj * 64, mrow = mg * 32;
    const int r = lane >> 2, q = lane & 3;
    const int tile = lane >> 3, lrow = lane & 7;

    for (int i = tx; i < 2048; i += 256) {              // 256 rows * 8 uint4
        int row = i >> 3, c = i & 7;
        ((uint4*)(s_w + row * KHW))[c] = ((const uint4*)wx)[i];
    }
    s_b[tx] = bs[tx];
    for (int i = tx; i < 512; i += 256) {               // 64 rows * 8 uint4
        int row = i >> 3, c = i & 7;
        int node = base + row;
        uint4 v = make_uint4(0u, 0u, 0u, 0u);
        if (node < N) v = ((const uint4*)(xp + (size_t)node * 64))[c];
        ((uint4*)(s_a + row * KHW))[c] = v;
    }
    __syncthreads();

    const uint32_t s_a_u = (uint32_t)__cvta_generic_to_shared(s_a);
    const uint32_t s_w_u = (uint32_t)__cvta_generic_to_shared(s_w);
    uint32_t aaddr[2], baddr[4];
    #pragma unroll
    for (int mt = 0; mt < 2; mt++)
        aaddr[mt] = s_a_u + 2 * ((mrow + mt * 16 + (tile & 1) * 8 + lrow) * KHW + (tile >> 1) * 8);
    #pragma unroll
    for (int np = 0; np < 4; np++)
        baddr[np] = s_w_u + 2 * ((nwb + np * 16 + (tile >> 1) * 8 + lrow) * KHW + (tile & 1) * 8);

    float acc[2][8][4];
    #pragma unroll
    for (int mt = 0; mt < 2; mt++)
        #pragma unroll
        for (int nt = 0; nt < 8; nt++) {
            float b0 = s_b[nwb + nt * 8 + 2 * q], b1 = s_b[nwb + nt * 8 + 2 * q + 1];
            acc[mt][nt][0] = b0; acc[mt][nt][1] = b1;
            acc[mt][nt][2] = b0; acc[mt][nt][3] = b1;
        }
    #pragma unroll
    for (int kc = 0; kc < 4; kc++) {
        const uint32_t ko = kc * 32;
        uint32_t af[2][4];
        LDSM_X4(af[0], aaddr[0] + ko);
        LDSM_X4(af[1], aaddr[1] + ko);
        #pragma unroll
        for (int np = 0; np < 4; np++) {
            uint32_t bf[4];
            LDSM_X4(bf, baddr[np] + ko);
            MMA_F16(acc[0][2 * np],     af[0], bf[0], bf[1]);
            MMA_F16(acc[1][2 * np],     af[1], bf[0], bf[1]);
            MMA_F16(acc[0][2 * np + 1], af[0], bf[2], bf[3]);
            MMA_F16(acc[1][2 * np + 1], af[1], bf[2], bf[3]);
        }
    }
    const int gpos = (nj * 4 + q) << 4;
    #pragma unroll
    for (int mt = 0; mt < 2; mt++)
        #pragma unroll
        for (int rr = 0; rr < 2; rr++) {
            int node = base + mrow + mt * 16 + r + 8 * rr;
            if (node < N) {
                uint32_t hv[8];
                #pragma unroll
                for (int nt = 0; nt < 8; nt++) {
                    __half2 h = __floats2half2_rn(acc[mt][nt][rr * 2 + 0], acc[mt][nt][rr * 2 + 1]);
                    hv[nt] = *(uint32_t*)&h;
                }
                uint4* dst = (uint4*)(xg + (size_t)node * 256 + gpos);
                dst[0] = make_uint4(hv[0], hv[1], hv[2], hv[3]);
                dst[1] = make_uint4(hv[4], hv[5], hv[6], hv[7]);
            }
        }
}

// ---------------- fused LSTM-SAGE kernel (K=64, ping-pong h, reg acc-init) --------
// Block = 64 nodes, 256 threads = 8 warps, warp grid 2(m32) x 4(n64), 2 CTA/SM.
// Acc init: 2x LDG.128/row/thread straight from L2-resident xg (no smem staging).
// Ping-pong h buffers -> ONE barrier per step.
template<int OUT>
__global__ __launch_bounds__(256, 2)
void lstm_mma_kernel(const __half* __restrict__ xg,
                     const float*  __restrict__ xin,
                     const int*    __restrict__ src,
                     const __half* __restrict__ whc,    // [256][64] permuted
                     const __half* __restrict__ wohi,   // [OUT][128]
                     const __half* __restrict__ wolo,
                     const float*  __restrict__ ob,
                     float* __restrict__ out,
                     int N) {
    extern __shared__ __half smh[];
    __half* s_wh = smh;                          // phase A: 0..18432
    __half* s_h0 = smh + 18432;                  // ..23040
    __half* s_h1 = smh + 23040;                  // ..27648
    __half* s_woh = smh;                         // phase B
    __half* s_wol = smh + OUT * KH128;
    __half* s_ih  = smh + 2 * OUT * KH128;
    __half* s_il  = s_ih + 64 * KH128;
    float*  s_ob  = (float*)(smh + 52224);
    int*    s_src = (int*)(s_ob + 256);

    const int tx = threadIdx.x;
    const int base = blockIdx.x * 64;
    const int lane = tx & 31, w = tx >> 5;
    const int mg = w >> 2, nj = w & 3;
    const int nwb = nj * 64;
    const int mrow = mg * 32;
    const int r = lane >> 2, q = lane & 3;
    const int tile = lane >> 3, lrow = lane & 7;

    // Wh -> smem [p][k]
    for (int i = tx; i < 2048; i += 256) {               // 256 rows * 8 uint4
        int row = i >> 3, c = i & 7;
        ((uint4*)(s_wh + row * KHW))[c] = ((const uint4*)whc)[i];
    }
    for (int i = tx; i < 1024; i += 256) {
        int node = base + (i >> 4);
        s_src[i] = (node < N) ? src[node * KDEG + (i & 15)] : 0;
    }
    // zero h0 (first step reads it)
    for (int i = tx; i < (64 * KHW) / 8; i += 256)
        ((uint4*)s_h0)[i] = make_uint4(0u, 0u, 0u, 0u);
    __syncthreads();

    float cst[2][4][2];
    #pragma unroll
    for (int a = 0; a < 2; a++)
        #pragma unroll
        for (int bb = 0; bb < 4; bb++) { cst[a][bb][0] = 0.f; cst[a][bb][1] = 0.f; }

    const uint32_t whu = (uint32_t)__cvta_generic_to_shared(s_wh);
    uint32_t hplane[2] = { (uint32_t)__cvta_generic_to_shared(s_h0),
                           (uint32_t)__cvta_generic_to_shared(s_h1) };
    uint32_t aoff[2], baddr[4];
    #pragma unroll
    for (int mt = 0; mt < 2; mt++)
        aoff[mt] = 2 * ((mrow + mt * 16 + (tile & 1) * 8 + lrow) * KHW + (tile >> 1) * 8);
    #pragma unroll
    for (int np = 0; np < 4; np++)
        baddr[np] = whu + 2 * ((nwb + np * 16 + (tile >> 1) * 8 + lrow) * KHW + (tile & 1) * 8);

    const int gpos = (nj * 4 + q) << 4;

    for (int t = 0; t < KDEG; t++) {
        __syncthreads();   // prior step's activation (h) fully visible

        // acc init: x-part (incl. bias) straight from L2 -> registers
        float acc[2][8][4];
        #pragma unroll
        for (int mt = 0; mt < 2; mt++)
            #pragma unroll
            for (int rr = 0; rr < 2; rr++) {
                int rowidx = mrow + mt * 16 + r + 8 * rr;
                int sn = s_src[rowidx * KDEG + t];
                const uint4* gp = (const uint4*)(xg + (size_t)sn * 256 + gpos);
                uint4 v0 = gp[0], v1 = gp[1];
                const uint32_t* pv = (const uint32_t*)&v0;
                #pragma unroll
                for (int j = 0; j < 4; j++) {
                    float2 f = __half22float2(*(const __half2*)&pv[j]);
                    acc[mt][j][rr * 2 + 0] = f.x;
                    acc[mt][j][rr * 2 + 1] = f.y;
                }
                const uint32_t* pw = (const uint32_t*)&v1;
                #pragma unroll
                for (int j = 0; j < 4; j++) {
                    float2 f = __half22float2(*(const __half2*)&pw[j]);
                    acc[mt][4 + j][rr * 2 + 0] = f.x;
                    acc[mt][4 + j][rr * 2 + 1] = f.y;
                }
            }

        // recurrent GEMM: += h_{t-1} @ Wh^T   (K = 64)
        const uint32_t hb = hplane[t & 1];
        #pragma unroll
        for (int kc = 0; kc < 4; kc++) {
            const uint32_t ko = kc * 32;
            uint32_t af[2][4];
            LDSM_X4(af[0], hb + aoff[0] + ko);
            LDSM_X4(af[1], hb + aoff[1] + ko);
            #pragma unroll
            for (int np = 0; np < 4; np++) {
                uint32_t bf[4];
                LDSM_X4(bf, baddr[np] + ko);
                MMA_F16(acc[0][2 * np],     af[0], bf[0], bf[1]);
                MMA_F16(acc[1][2 * np],     af[1], bf[0], bf[1]);
                MMA_F16(acc[0][2 * np + 1], af[0], bf[2], bf[3]);
                MMA_F16(acc[1][2 * np + 1], af[1], bf[2], bf[3]);
            }
        }
        const bool last = (t == KDEG - 1);
        if (last) __syncthreads();   // all smem reads done before writing phase-B region

        // activation: f16x2 tanh path, c-state fp32
        __half* hn = ((t + 1) & 1) ? s_h1 : s_h0;
        #pragma unroll
        for (int mt = 0; mt < 2; mt++) {
            #pragma unroll
            for (int rr = 0; rr < 2; rr++) {
                int row = mrow + mt * 16 + r + 8 * rr;
                __half2* dst = last
                    ? (__half2*)(s_ih + row * KH128 + 64 + nj * 16 + q * 4)
                    : (__half2*)(hn + row * KHW + nj * 16 + q * 4);
                #pragma unroll
                for (int p = 0; p < 2; p++) {
                    int t0 = 2 * p, t1 = 2 * p + 1;
                    __half2 i2 = __floats2half2_rn(acc[mt][2 * t0][rr * 2 + 0], acc[mt][2 * t1][rr * 2 + 0]);
                    __half2 f2 = __floats2half2_rn(acc[mt][2 * t0][rr * 2 + 1], acc[mt][2 * t1][rr * 2 + 1]);
                    __half2 g2 = __floats2half2_rn(acc[mt][2 * t0 + 1][rr * 2 + 0], acc[mt][2 * t1 + 1][rr * 2 + 0]);
                    __half2 o2 = __floats2half2_rn(acc[mt][2 * t0 + 1][rr * 2 + 1], acc[mt][2 * t1 + 1][rr * 2 + 1]);
                    __half2 si = sig2(i2), sf = sig2(f2), so = sig2(o2), tg = tanh2(g2);
                    float2 fi = __half22float2(si), ff = __half22float2(sf), fg = __half22float2(tg);
                    float c0 = ff.x * cst[mt][t0][rr] + fi.x * fg.x;
                    float c1 = ff.y * cst[mt][t1][rr] + fi.y * fg.y;
                    cst[mt][t0][rr] = c0; cst[mt][t1][rr] = c1;
                    __half2 tc = tanh2(__floats2half2_rn(c0, c1));
                    dst[p] = __hmul2(so, tc);
                }
            }
        }
    }
    __syncthreads();   // phase A fully consumed; s_ih h-cols written

    // ---- fused SAGE output, split fp16: out = relu([x||h]*Wo^T + ob) ----
    constexpr int NT2 = OUT / 32;
    const int nwb2 = nj * (OUT / 4);

    for (int i = tx; i < OUT * 16; i += 256) {           // OUT rows * 16 uint4
        int row = i >> 4, c = i & 15;
        ((uint4*)(s_woh + row * KH128))[c] = ((const uint4*)wohi)[i];
        ((uint4*)(s_wol + row * KH128))[c] = ((const uint4*)wolo)[i];
    }
    for (int i = tx; i < OUT; i += 256) s_ob[i] = ob[i];
    // zero il h-cols (64..127): 64 rows * 8 uint4
    for (int i = tx; i < 512; i += 256) {
        int row = i >> 3, c = i & 7;
        ((uint4*)(s_il + row * KH128 + 64))[c] = make_uint4(0u, 0u, 0u, 0u);
    }
    // xin -> hi/lo planes (x cols 0..63); h cols: hi written by last activation
    #pragma unroll
    for (int i = 0; i < 4; i++) {
        int idx = tx + i * 256;                          // 64 rows * 16 float4
        int n = idx >> 4, c = idx & 15;
        int node = base + n;
        float4 v = make_float4(0.f, 0.f, 0.f, 0.f);
        if (node < N) v = ((const float4*)(xin + (size_t)node * 64))[c];
        __half2 h0 = __floats2half2_rn(v.x, v.y), h1 = __floats2half2_rn(v.z, v.w);
        float2 f0 = __half22float2(h0), f1 = __half22float2(h1);
        __half2* dh = (__half2*)(s_ih + n * KH128 + c * 4);
        __half2* dl = (__half2*)(s_il + n * KH128 + c * 4);
        dh[0] = h0; dh[1] = h1;
        dl[0] = __floats2half2_rn(v.x - f0.x, v.y - f0.y);
        dl[1] = __floats2half2_rn(v.z - f1.x, v.w - f1.y);
    }
    __syncthreads();

    float a2[2][NT2][4];
    #pragma unroll
    for (int mt = 0; mt < 2; mt++)
        #pragma unroll
        for (int nt = 0; nt < NT2; nt++) {
            int c0 = nwb2 + nt * 8 + 2 * q;
            a2[mt][nt][0] = s_ob[c0];     a2[mt][nt][1] = s_ob[c0 + 1];
            a2[mt][nt][2] = s_ob[c0];     a2[mt][nt][3] = s_ob[c0 + 1];
        }
    #pragma unroll 2
    for (int kc = 0; kc < 8; kc++) {
        const int kw = kc * 8;
        uint32_t ah[2][4], al[2][4];
        #pragma unroll
        for (int mt = 0; mt < 2; mt++) {
            const uint32_t* ap = (const uint32_t*)s_ih + (mrow + mt * 16 + r) * WS128 + kw + q;
            const uint32_t* lp = (const uint32_t*)s_il + (mrow + mt * 16 + r) * WS128 + kw + q;
            ah[mt][0] = ap[0]; ah[mt][1] = ap[8 * WS128]; ah[mt][2] = ap[4]; ah[mt][3] = ap[8 * WS128 + 4];
            al[mt][0] = lp[0]; al[mt][1] = lp[8 * WS128]; al[mt][2] = lp[4]; al[mt][3] = lp[8 * WS128 + 4];
        }
        #pragma unroll
        for (int nt = 0; nt < NT2; nt++) {
            const uint32_t* bh = (const uint32_t*)s_woh + (nwb2 + nt * 8 + r) * WS128 + kw + q;
            const uint32_t* bl = (const uint32_t*)s_wol + (nwb2 + nt * 8 + r) * WS128 + kw + q;
            uint32_t bh0 = bh[0], bh1 = bh[4], bl0 = bl[0], bl1 = bl[4];
            #pragma unroll
            for (int mt = 0; mt < 2; mt++) {
                MMA_F16(a2[mt][nt], ah[mt], bh0, bh1);
                MMA_F16(a2[mt][nt], ah[mt], bl0, bl1);
                MMA_F16(a2[mt][nt], al[mt], bh0, bh1);
            }
        }
    }
    #pragma unroll
    for (int mt = 0; mt < 2; mt++)
        #pragma unroll
        for (int nt = 0; nt < NT2; nt++)
            #pragma unroll
            for (int rr = 0; rr < 2; rr++) {
                int node = base + mrow + mt * 16 + r + 8 * rr;
                if (node < N) {
                    int c0 = nwb2 + nt * 8 + 2 * q;
                    float2 v;
                    v.x = fmaxf(a2[mt][nt][2 * rr + 0], 0.f);
                    v.y = fmaxf(a2[mt][nt][2 * rr + 1], 0.f);
                    *(float2*)(out + (size_t)node * OUT + c0) = v;
                }
            }
}

// ---------------- split-fp16 MMA linear + relu ----------------
template<int KIN, int KOUT, bool HOUT>
__global__ __launch_bounds__(256, 1)
void mma_linear(const float* __restrict__ A,
                const __half* __restrict__ Whi, const __half* __restrict__ Wlo,
                const float* __restrict__ bias, void* __restrict__ outp, int N) {
    constexpr int KH = KIN + 8, WSL = KH / 2, CH = KIN / 16;
    constexpr int NT = KOUT / 32;
    extern __shared__ __half sh[];
    __half* s_wh = sh;
    __half* s_wl = s_wh + KOUT * KH;
    __half* s_ah = s_wl + KOUT * KH;
    __half* s_al = s_ah + 128 * KH;
    float*  s_b  = (float*)(s_al + 128 * KH);

    const int tx = threadIdx.x, base = blockIdx.x * 128;
    const int lane = tx & 31, w = tx >> 5;
    const int mg = w >> 2, nj = w & 3;
    const int r = lane >> 2, q = lane & 3;
    const int mrow = mg * 64, nwb = nj * (KOUT / 4);

    for (int i = tx; i < KOUT * (KIN / 8); i += 256) {
        int row = i / (KIN / 8), c = i % (KIN / 8);
        ((uint4*)(s_wh + row * KH))[c] = ((const uint4*)Whi)[i];
        ((uint4*)(s_wl + row * KH))[c] = ((const uint4*)Wlo)[i];
    }
    for (int i = tx; i < KOUT; i += 256) s_b[i] = bias[i];
    for (int i = tx; i < 128 * (KIN / 4); i += 256) {
        int n = i / (KIN / 4), c = i % (KIN / 4);
        int node = base + n;
        float4 v = make_float4(0.f, 0.f, 0.f, 0.f);
        if (node < N) v = ((const float4*)(A + (size_t)node * KIN))[c];
        __half2 h0 = __floats2half2_rn(v.x, v.y), h1 = __floats2half2_rn(v.z, v.w);
        float2 f0 = __half22float2(h0), f1 = __half22float2(h1);
        __half2* dh = (__half2*)(s_ah + n * KH + c * 4);
        __half2* dl = (__half2*)(s_al + n * KH + c * 4);
        dh[0] = h0; dh[1] = h1;
        dl[0] = __floats2half2_rn(v.x - f0.x, v.y - f0.y);
        dl[1] = __floats2half2_rn(v.z - f1.x, v.w - f1.y);
    }
    __syncthreads();

    float acc[4][NT][4];
    #pragma unroll
    for (int mt = 0; mt < 4; mt++)
        #pragma unroll
        for (int nt = 0; nt < NT; nt++) {
            int c0 = nwb + nt * 8 + 2 * q;
            acc[mt][nt][0] = s_b[c0];     acc[mt][nt][1] = s_b[c0 + 1];
            acc[mt][nt][2] = s_b[c0];     acc[mt][nt][3] = s_b[c0 + 1];
        }
    #pragma unroll 2
    for (int kc = 0; kc < CH; kc++) {
        const int kw = kc * 8;
        uint32_t ah[4][4], al[4][4];
        #pragma unroll
        for (int mt = 0; mt < 4; mt++) {
            const uint32_t* ap = (const uint32_t*)s_ah + (mrow + mt * 16 + r) * WSL + kw + q;
            const uint32_t* lp = (const uint32_t*)s_al + (mrow + mt * 16 + r) * WSL + kw + q;
            ah[mt][0] = ap[0]; ah[mt][1] = ap[8 * WSL]; ah[mt][2] = ap[4]; ah[mt][3] = ap[8 * WSL + 4];
            al[mt][0] = lp[0]; al[mt][1] = lp[8 * WSL]; al[mt][2] = lp[4]; al[mt][3] = lp[8 * WSL + 4];
        }
        #pragma unroll
        for (int nt = 0; nt < NT; nt++) {
            const uint32_t* bh = (const uint32_t*)s_wh + (nwb + nt * 8 + r) * WSL + kw + q;
            const uint32_t* bl = (const uint32_t*)s_wl + (nwb + nt * 8 + r) * WSL + kw + q;
            uint32_t bh0 = bh[0], bh1 = bh[4], bl0 = bl[0], bl1 = bl[4];
            #pragma unroll
            for (int mt = 0; mt < 4; mt++) {
                MMA_F16(acc[mt][nt], ah[mt], bh0, bh1);
                MMA_F16(acc[mt][nt], ah[mt], bl0, bl1);
                MMA_F16(acc[mt][nt], al[mt], bh0, bh1);
            }
        }
    }
    #pragma unroll
    for (int mt = 0; mt < 4; mt++)
        #pragma unroll
        for (int nt = 0; nt < NT; nt++)
            #pragma unroll
            for (int rr = 0; rr < 2; rr++) {
                int node = base + mrow + mt * 16 + r + 8 * rr;
                if (node < N) {
                    int c0 = nwb + nt * 8 + 2 * q;
                    float vx = fmaxf(acc[mt][nt][2 * rr + 0], 0.f);
                    float vy = fmaxf(acc[mt][nt][2 * rr + 1], 0.f);
                    if (HOUT) {
                        *(__half2*)((__half*)outp + (size_t)node * KOUT + c0) =
                            __floats2half2_rn(vx, vy);
                    } else {
                        *(float2*)((float*)outp + (size_t)node * KOUT + c0) =
                            make_float2(vx, vy);
                    }
                }
            }
}

// ---------------- host launcher ----------------
static void* symaddr(const void* sym) {
    void* p = nullptr;
    cudaGetSymbolAddress(&p, sym);
    return p;
}

extern "C" void kernel_launch(void* const* d_in, const int* in_sizes, int n_in,
                              void* d_out, int out_size) {
    const float* x   = (const float*)d_in[0];
    const int*   ei  = (const int*)d_in[1];
    const int N = in_sizes[0] / 64;
    const int E = in_sizes[1] / 2;
    const int* src = ei;

    const float* p1pw  = (const float*)d_in[3];
    const float* p1pb  = (const float*)d_in[4];
    const float* p1wih = (const float*)d_in[5];
    const float* p1whh = (const float*)d_in[6];
    const float* p1bih = (const float*)d_in[7];
    const float* p1bhh = (const float*)d_in[8];
    const float* p1llw = (const float*)d_in[9];
    const float* p1llb = (const float*)d_in[10];
    const float* p1lrw = (const float*)d_in[11];
    const float* p2pw  = (const float*)d_in[12];
    const float* p2pb  = (const float*)d_in[13];
    const float* p2wih = (const float*)d_in[14];
    const float* p2whh = (const float*)d_in[15];
    const float* p2bih = (const float*)d_in[16];
    const float* p2bhh = (const float*)d_in[17];
    const float* p2llw = (const float*)d_in[18];
    const float* p2llb = (const float*)d_in[19];
    const float* p2lrw = (const float*)d_in[20];
    const float* l1w   = (const float*)d_in[21];
    const float* l1b   = (const float*)d_in[22];
    const float* l2w   = (const float*)d_in[23];
    const float* l2b   = (const float*)d_in[24];
    const float* l3w   = (const float*)d_in[25];
    const float* l3b   = (const float*)d_in[26];

    __half* xp  = (__half*)symaddr(g_xp);
    __half* xg  = (__half*)symaddr(g_xg);
    float*  h1  = (float*)symaddr(g_h1);
    float*  h2  = (float*)symaddr(g_h2);
    float*  t1  = (float*)symaddr(g_t1);
    float*  t2  = (float*)symaddr(g_t2);
    __half* wx1 = (__half*)symaddr(g_wx1);
    __half* wh1 = (__half*)symaddr(g_wh1);
    __half* wx2 = (__half*)symaddr(g_wx2);
    __half* wh2 = (__half*)symaddr(g_wh2);
    float*  bs1 = (float*)symaddr(g_bs1);
    float*  bs2 = (float*)symaddr(g_bs2);
    __half* wo1h = (__half*)symaddr(g_wo1h); __half* wo1l = (__half*)symaddr(g_wo1l);
    __half* wo2h = (__half*)symaddr(g_wo2h); __half* wo2l = (__half*)symaddr(g_wo2l);
    __half* pT1h = (__half*)symaddr(g_pT1h); __half* pT1l = (__half*)symaddr(g_pT1l);
    __half* pT2h = (__half*)symaddr(g_pT2h); __half* pT2l = (__half*)symaddr(g_pT2l);
    __half* l1h  = (__half*)symaddr(g_l1h);  __half* l1l  = (__half*)symaddr(g_l1l);
    __half* l2h  = (__half*)symaddr(g_l2h);  __half* l2l  = (__half*)symaddr(g_l2l);
    __half* l3h  = (__half*)symaddr(g_l3h);  __half* l3l  = (__half*)symaddr(g_l3l);

    // smem sizes
    const int SM_LSTM = 52224 * 2 + 256 * 4 + 1024 * 4;                          // 109568
    const int SM_XG   = (256 * KHW + 64 * KHW) * 2 + 256 * 4;                    // 47104
    const int SM_6464 = (2 * 64 * 72 + 2 * 128 * 72) * 2 + 64 * 4;               // 55552
    const int SM_L1   = (2 * 192 * 136 + 2 * 128 * 136) * 2 + 192 * 4;           // 174848
    const int SM_L2   = (2 * 64 * 200 + 2 * 128 * 200) * 2 + 64 * 4;             // 153856
    cudaFuncSetAttribute(lstm_mma_kernel<64>,        cudaFuncAttributeMaxDynamicSharedMemorySize, SM_LSTM);
    cudaFuncSetAttribute(lstm_mma_kernel<128>,       cudaFuncAttributeMaxDynamicSharedMemorySize, SM_LSTM);
    cudaFuncSetAttribute(xg_kernel,                  cudaFuncAttributeMaxDynamicSharedMemorySize, SM_XG);
    cudaFuncSetAttribute(mma_linear<64, 64, true>,   cudaFuncAttributeMaxDynamicSharedMemorySize, SM_6464);
    cudaFuncSetAttribute(mma_linear<64, 64, false>,  cudaFuncAttributeMaxDynamicSharedMemorySize, SM_6464);
    cudaFuncSetAttribute(mma_linear<128, 192, false>, cudaFuncAttributeMaxDynamicSharedMemorySize, SM_L1);
    cudaFuncSetAttribute(mma_linear<192, 64, false>, cudaFuncAttributeMaxDynamicSharedMemorySize, SM_L2);

    // --- fused weight prep ---
    k_prep_all<<<544, 256>>>(p1wih, p1whh, p1bih, p1bhh,
                             p2wih, p2whh, p2bih, p2bhh,
                             p1llw, p1lrw, p2llw, p2lrw,
                             p1pw, p2pw, l1w, l2w, l3w);

    const int NB128 = (N + 127) / 128;
    const int NB64  = (N + 63) / 64;

    // --- layer 1 ---
    mma_linear<64, 64, true><<<NB128, 256, SM_6464>>>(x, pT1h, pT1l, p1pb, xp, N);
    xg_kernel<<<NB64, 256, SM_XG>>>(xp, wx1, bs1, xg, N);
    lstm_mma_kernel<64><<<NB64, 256, SM_LSTM>>>(xg, x, src, wh1, wo1h, wo1l, p1llb, h1, N);
    // --- layer 2 ---
    mma_linear<64, 64, true><<<NB128, 256, SM_6464>>>(h1, pT2h, pT2l, p2pb, xp, N);
    xg_kernel<<<NB64, 256, SM_XG>>>(xp, wx2, bs2, xg, N);
    lstm_mma_kernel<128><<<NB64, 256, SM_LSTM>>>(xg, h1, src, wh2, wo2h, wo2l, p2llb, h2, N);
    // --- MLP head ---
    mma_linear<128, 192, false><<<NB128, 256, SM_L1>>>(h2, l1h, l1l, l1b, t1, N);
    mma_linear<192, 64, false><<<NB128, 256, SM_L2>>>(t1, l2h, l2l, l2b, t2, N);
    mma_linear<64, 64, false><<<NB128, 256, SM_6464>>>(t2, l3h, l3l, l3b, d_out, N);

    // --- edge_index passthrough if the output buffer holds it ---
    long hsz = (long)N * 64;
    if ((long)out_size > hsz) {
        long remaining = (long)out_size - hsz;
        int count = (int)((remaining < (long)2 * E) ? remaining : (long)2 * E);
        k_edge_copy<<<(count + 255) / 256, 256>>>(ei, (float*)d_out + hsz, count);
    }
}

// round 14
// speedup vs baseline: 1.2407x; 1.0214x over previous
#include <cuda_runtime.h>
#include <cuda_fp16.h>
#include <cstdint>

// Problem constants (fixed-shape problem)
#define MAXN 50000
#define KDEG 16

#define KHW   72     // W / h row stride in halves (64 + 8 pad) -> conflict-free
#define KH128 136    // [x||h] row stride in halves
#define WS128 68     // word stride of KH128

// ---------------- scratch (device globals: allocation-free) ----------------
__device__ __half g_xp [MAXN * 64];     // projected feats, fp16
__device__ __half g_xg [MAXN * 256];    // Wx*xp + b, fragment-ordered, fp16
__device__ float  g_hb [MAXN * 64];     // LSTM final h, fp32
__device__ float  g_h1 [MAXN * 64];
__device__ float  g_h2 [MAXN * 128];
__device__ float  g_t1 [MAXN * 192];
__device__ float  g_t2 [MAXN * 64];

__device__ __half g_wx1 [256 * 64];     // permuted Wx [pcol][k]
__device__ __half g_wh1 [256 * 64];     // permuted Wh [pcol][k]
__device__ __half g_wx2 [256 * 64];
__device__ __half g_wh2 [256 * 64];
__device__ float  g_bs1 [256];          // permuted bih+bhh
__device__ float  g_bs2 [256];
__device__ __half g_wo1h[64 * 128],  g_wo1l[64 * 128];
__device__ __half g_wo2h[128 * 128], g_wo2l[128 * 128];
__device__ __half g_pT1h[64 * 64],   g_pT1l[64 * 64];
__device__ __half g_pT2h[64 * 64],   g_pT2l[64 * 64];
__device__ __half g_l1h [192 * 128], g_l1l [192 * 128];
__device__ __half g_l2h [64 * 192],  g_l2l [64 * 192];
__device__ __half g_l3h [64 * 64],   g_l3l [64 * 64];

// ---------------- helpers ----------------
__device__ __forceinline__ __half2 tanh2(__half2 x) {
    __half2 y;
    asm("tanh.approx.f16x2 %0, %1;" : "=r"(*(uint32_t*)&y) : "r"(*(const uint32_t*)&x));
    return y;
}
__device__ __forceinline__ __half2 sig2(__half2 x) {
    const __half2 h05 = __float2half2_rn(0.5f);
    return __hfma2(tanh2(__hmul2(x, h05)), h05, h05);
}

#define MMA_F16(D, A, b0, b1)                                                   \
    asm volatile("mma.sync.aligned.m16n8k16.row.col.f32.f16.f16.f32 "           \
                 "{%0,%1,%2,%3}, {%4,%5,%6,%7}, {%8,%9}, {%0,%1,%2,%3};"        \
                 : "+f"(D[0]), "+f"(D[1]), "+f"(D[2]), "+f"(D[3])               \
                 : "r"(A[0]), "r"(A[1]), "r"(A[2]), "r"(A[3]), "r"(b0), "r"(b1));

#define LDSM_X4(R, addr)                                                        \
    asm volatile("ldmatrix.sync.aligned.m8n8.x4.shared.b16 {%0,%1,%2,%3}, [%4];"\
                 : "=r"((R)[0]), "=r"((R)[1]), "=r"((R)[2]), "=r"((R)[3])       \
                 : "r"(addr));

// Gate-column permutation: each thread's accumulator fragment owns the full
// (i,f,g,o) quadruple for its hidden units.
__device__ __forceinline__ int perm_orig_col(int p) {
    int nj = p >> 6, rr = p & 63;
    int tp = rr >> 4, r2 = rr & 15;
    int half_ = r2 >> 3, r3 = r2 & 7;
    int q = r3 >> 1, low = r3 & 1;
    int gate = half_ * 2 + low;             // 0=i 1=f 2=g 3=o
    int jg = nj * 16 + q * 4 + tp;
    return gate * 64 + jg;
}

__device__ __forceinline__ void wsplit(__half* hi, __half* lo, int idx, float v) {
    __half h = __float2half_rn(v);
    hi[idx] = h;
    lo[idx] = __float2half_rn(v - __half2float(h));
}

// ---------------- single fused prep kernel ----------------
__global__ void k_prep_all(
    const float* p1wih, const float* p1whh, const float* p1bih, const float* p1bhh,
    const float* p2wih, const float* p2whh, const float* p2bih, const float* p2bhh,
    const float* p1llw, const float* p1lrw, const float* p2llw, const float* p2lrw,
    const float* p1pw, const float* p2pw,
    const float* l1w, const float* l2w, const float* l3w) {
    int b = blockIdx.x, t = threadIdx.x;
    if (b < 64) {                        // wx1: 256x64
        int idx = b * 256 + t;
        int p = idx >> 6, k = idx & 63;
        g_wx1[idx] = __float2half_rn(p1wih[perm_orig_col(p) * 64 + k]);
        if (idx < 256) { int g2 = perm_orig_col(idx); g_bs1[idx] = p1bih[g2] + p1bhh[g2]; }
    } else if (b < 128) {                // wh1
        int idx = (b - 64) * 256 + t;
        int p = idx >> 6, k = idx & 63;
        g_wh1[idx] = __float2half_rn(p1whh[perm_orig_col(p) * 64 + k]);
    } else if (b < 192) {                // wx2
        int idx = (b - 128) * 256 + t;
        int p = idx >> 6, k = idx & 63;
        g_wx2[idx] = __float2half_rn(p2wih[perm_orig_col(p) * 64 + k]);
        if (idx < 256) { int g2 = perm_orig_col(idx); g_bs2[idx] = p2bih[g2] + p2bhh[g2]; }
    } else if (b < 256) {                // wh2
        int idx = (b - 192) * 256 + t;
        int p = idx >> 6, k = idx & 63;
        g_wh2[idx] = __float2half_rn(p2whh[perm_orig_col(p) * 64 + k]);
    } else if (b < 288) {                // wo1: 64x128
        int idx = (b - 256) * 256 + t;
        int o = idx >> 7, k = idx & 127;
        wsplit(g_wo1h, g_wo1l, idx, k < 64 ? p1lrw[o * 64 + k] : p1llw[o * 64 + (k - 64)]);
    } else if (b < 352) {                // wo2: 128x128
        int idx = (b - 288) * 256 + t;
        int o = idx >> 7, k = idx & 127;
        wsplit(g_wo2h, g_wo2l, idx, k < 64 ? p2lrw[o * 64 + k] : p2llw[o * 64 + (k - 64)]);
    } else if (b < 368) {                // pT1
        int idx = (b - 352) * 256 + t;
        wsplit(g_pT1h, g_pT1l, idx, p1pw[idx]);
    } else if (b < 384) {                // pT2
        int idx = (b - 368) * 256 + t;
        wsplit(g_pT2h, g_pT2l, idx, p2pw[idx]);
    } else if (b < 480) {                // l1
        int idx = (b - 384) * 256 + t;
        wsplit(g_l1h, g_l1l, idx, l1w[idx]);
    } else if (b < 528) {                // l2
        int idx = (b - 480) * 256 + t;
        wsplit(g_l2h, g_l2l, idx, l2w[idx]);
    } else {                             // l3
        int idx = (b - 528) * 256 + t;
        wsplit(g_l3h, g_l3l, idx, l3w[idx]);
    }
}

__global__ void k_edge_copy(const int* __restrict__ ei, float* __restrict__ out, int count) {
    int i = blockIdx.x * blockDim.x + threadIdx.x;
    if (i < count) out[i] = (float)ei[i];
}

// ---------------- xg precompute: xg[n] = Wx(perm)·xp[n] + b, fragment-ordered fp16 ----
__global__ __launch_bounds__(256, 2)
void xg_kernel(const __half* __restrict__ xp, const __half* __restrict__ wx,
               const float* __restrict__ bs, __half* __restrict__ xg, int N) {
    extern __shared__ __half sh[];
    __half* s_w = sh;                    // 256*KHW
    __half* s_a = s_w + 256 * KHW;       // 64*KHW
    float*  s_b = (float*)(s_a + 64 * KHW);

    const int tx = threadIdx.x, base = blockIdx.x * 64;
    const int lane = tx & 31, w = tx >> 5;
    const int mg = w >> 2, nj = w & 3;
    const int nwb = nj * 64, mrow = mg * 32;
    const int r = lane >> 2, q = lane & 3;
    const int tile = lane >> 3, lrow = lane & 7;

    for (int i = tx; i < 2048; i += 256) {
        int row = i >> 3, c = i & 7;
        ((uint4*)(s_w + row * KHW))[c] = ((const uint4*)wx)[i];
    }
    s_b[tx] = bs[tx];
    for (int i = tx; i < 512; i += 256) {
        int row = i >> 3, c = i & 7;
        int node = base + row;
        uint4 v = make_uint4(0u, 0u, 0u, 0u);
        if (node < N) v = ((const uint4*)(xp + (size_t)node * 64))[c];
        ((uint4*)(s_a + row * KHW))[c] = v;
    }
    __syncthreads();

    const uint32_t s_a_u = (uint32_t)__cvta_generic_to_shared(s_a);
    const uint32_t s_w_u = (uint32_t)__cvta_generic_to_shared(s_w);
    uint32_t aaddr[2], baddr[4];
    #pragma unroll
    for (int mt = 0; mt < 2; mt++)
        aaddr[mt] = s_a_u + 2 * ((mrow + mt * 16 + (tile & 1) * 8 + lrow) * KHW + (tile >> 1) * 8);
    #pragma unroll
    for (int np = 0; np < 4; np++)
        baddr[np] = s_w_u + 2 * ((nwb + np * 16 + (tile >> 1) * 8 + lrow) * KHW + (tile & 1) * 8);

    float acc[2][8][4];
    #pragma unroll
    for (int mt = 0; mt < 2; mt++)
        #pragma unroll
        for (int nt = 0; nt < 8; nt++) {
            float b0 = s_b[nwb + nt * 8 + 2 * q], b1 = s_b[nwb + nt * 8 + 2 * q + 1];
            acc[mt][nt][0] = b0; acc[mt][nt][1] = b1;
            acc[mt][nt][2] = b0; acc[mt][nt][3] = b1;
        }
    #pragma unroll
    for (int kc = 0; kc < 4; kc++) {
        const uint32_t ko = kc * 32;
        uint32_t af[2][4];
        LDSM_X4(af[0], aaddr[0] + ko);
        LDSM_X4(af[1], aaddr[1] + ko);
        #pragma unroll
        for (int np = 0; np < 4; np++) {
            uint32_t bf[4];
            LDSM_X4(bf, baddr[np] + ko);
            MMA_F16(acc[0][2 * np],     af[0], bf[0], bf[1]);
            MMA_F16(acc[1][2 * np],     af[1], bf[0], bf[1]);
            MMA_F16(acc[0][2 * np + 1], af[0], bf[2], bf[3]);
            MMA_F16(acc[1][2 * np + 1], af[1], bf[2], bf[3]);
        }
    }
    const int gpos = (nj * 4 + q) << 4;
    #pragma unroll
    for (int mt = 0; mt < 2; mt++)
        #pragma unroll
        for (int rr = 0; rr < 2; rr++) {
            int node = base + mrow + mt * 16 + r + 8 * rr;
            if (node < N) {
                uint32_t hv[8];
                #pragma unroll
                for (int nt = 0; nt < 8; nt++) {
                    __half2 h = __floats2half2_rn(acc[mt][nt][rr * 2 + 0], acc[mt][nt][rr * 2 + 1]);
                    hv[nt] = *(uint32_t*)&h;
                }
                uint4* dst = (uint4*)(xg + (size_t)node * 256 + gpos);
                dst[0] = make_uint4(hv[0], hv[1], hv[2], hv[3]);
                dst[1] = make_uint4(hv[4], hv[5], hv[6], hv[7]);
            }
        }
}

// ---------------- LSTM recurrence only (32 nodes/block, 4 CTA/SM) ----------------
// 128 threads = 4 warps = 1 per SMSP -> each SMSP interleaves 4 independent
// block recurrences. Final h written fp32 to hb[N,64].
__global__ __launch_bounds__(128, 4)
void lstm_rec(const __half* __restrict__ xg,
              const int*    __restrict__ src,
              const __half* __restrict__ whc,    // [256][64] permuted
              float* __restrict__ hb,            // [N,64] fp32 out
              int N) {
    extern __shared__ __half smh[];
    __half* s_wh = smh;                          // 256*KHW = 18432 halves
    __half* s_h0 = smh + 18432;                  // 32*KHW = 2304
    __half* s_h1 = smh + 20736;                  // 2304
    int*    s_src = (int*)(smh + 23040);         // 512 ints

    const int tx = threadIdx.x;
    const int base = blockIdx.x * 32;
    const int lane = tx & 31, nj = tx >> 5;      // 4 warps = 4 nj
    const int nwb = nj * 64;
    const int r = lane >> 2, q = lane & 3;
    const int tile = lane >> 3, lrow = lane & 7;

    for (int i = tx; i < 2048; i += 128) {       // Wh: 256 rows * 8 uint4
        int row = i >> 3, c = i & 7;
        ((uint4*)(s_wh + row * KHW))[c] = ((const uint4*)whc)[i];
    }
    for (int i = tx; i < 512; i += 128) {
        int node = base + (i >> 4);
        s_src[i] = (node < N) ? src[node * KDEG + (i & 15)] : 0;
    }
    for (int i = tx; i < (32 * KHW) / 8; i += 128)
        ((uint4*)s_h0)[i] = make_uint4(0u, 0u, 0u, 0u);
    __syncthreads();

    float cst[2][4][2];
    #pragma unroll
    for (int a = 0; a < 2; a++)
        #pragma unroll
        for (int bb = 0; bb < 4; bb++) { cst[a][bb][0] = 0.f; cst[a][bb][1] = 0.f; }

    const uint32_t whu = (uint32_t)__cvta_generic_to_shared(s_wh);
    uint32_t hplane[2] = { (uint32_t)__cvta_generic_to_shared(s_h0),
                           (uint32_t)__cvta_generic_to_shared(s_h1) };
    uint32_t aoff[2], baddr[4];
    #pragma unroll
    for (int mt = 0; mt < 2; mt++)
        aoff[mt] = 2 * ((mt * 16 + (tile & 1) * 8 + lrow) * KHW + (tile >> 1) * 8);
    #pragma unroll
    for (int np = 0; np < 4; np++)
        baddr[np] = whu + 2 * ((nwb + np * 16 + (tile >> 1) * 8 + lrow) * KHW + (tile & 1) * 8);

    const int gpos = (nj * 4 + q) << 4;

    for (int t = 0; t < KDEG; t++) {
        __syncthreads();   // prior step's h visible

        // acc init: x-part (incl. bias) straight from L2 -> registers
        float acc[2][8][4];
        #pragma unroll
        for (int mt = 0; mt < 2; mt++)
            #pragma unroll
            for (int rr = 0; rr < 2; rr++) {
                int rowidx = mt * 16 + r + 8 * rr;
                int sn = s_src[rowidx * KDEG + t];
                const uint4* gp = (const uint4*)(xg + (size_t)sn * 256 + gpos);
                uint4 v0 = gp[0], v1 = gp[1];
                const uint32_t* pv = (const uint32_t*)&v0;
                #pragma unroll
                for (int j = 0; j < 4; j++) {
                    float2 f = __half22float2(*(const __half2*)&pv[j]);
                    acc[mt][j][rr * 2 + 0] = f.x;
                    acc[mt][j][rr * 2 + 1] = f.y;
                }
                const uint32_t* pw = (const uint32_t*)&v1;
                #pragma unroll
                for (int j = 0; j < 4; j++) {
                    float2 f = __half22float2(*(const __half2*)&pw[j]);
                    acc[mt][4 + j][rr * 2 + 0] = f.x;
                    acc[mt][4 + j][rr * 2 + 1] = f.y;
                }
            }

        // recurrent GEMM: += h_{t-1} @ Wh^T   (K = 64)
        const uint32_t hbse = hplane[t & 1];
        #pragma unroll
        for (int kc = 0; kc < 4; kc++) {
            const uint32_t ko = kc * 32;
            uint32_t af[2][4];
            LDSM_X4(af[0], hbse + aoff[0] + ko);
            LDSM_X4(af[1], hbse + aoff[1] + ko);
            #pragma unroll
            for (int np = 0; np < 4; np++) {
                uint32_t bf[4];
                LDSM_X4(bf, baddr[np] + ko);
                MMA_F16(acc[0][2 * np],     af[0], bf[0], bf[1]);
                MMA_F16(acc[1][2 * np],     af[1], bf[0], bf[1]);
                MMA_F16(acc[0][2 * np + 1], af[0], bf[2], bf[3]);
                MMA_F16(acc[1][2 * np + 1], af[1], bf[2], bf[3]);
            }
        }

        // activation: f16x2 tanh path, c-state fp32
        const bool last = (t == KDEG - 1);
        __half* hn = ((t + 1) & 1) ? s_h1 : s_h0;
        #pragma unroll
        for (int mt = 0; mt < 2; mt++) {
            #pragma unroll
            for (int rr = 0; rr < 2; rr++) {
                int row = mt * 16 + r + 8 * rr;
                __half2* dst = (__half2*)(hn + row * KHW + nj * 16 + q * 4);
                float4 hv4;
                float* hvp = (float*)&hv4;
                #pragma unroll
                for (int p = 0; p < 2; p++) {
                    int t0 = 2 * p, t1 = 2 * p + 1;
                    __half2 i2 = __floats2half2_rn(acc[mt][2 * t0][rr * 2 + 0], acc[mt][2 * t1][rr * 2 + 0]);
                    __half2 f2 = __floats2half2_rn(acc[mt][2 * t0][rr * 2 + 1], acc[mt][2 * t1][rr * 2 + 1]);
                    __half2 g2 = __floats2half2_rn(acc[mt][2 * t0 + 1][rr * 2 + 0], acc[mt][2 * t1 + 1][rr * 2 + 0]);
                    __half2 o2 = __floats2half2_rn(acc[mt][2 * t0 + 1][rr * 2 + 1], acc[mt][2 * t1 + 1][rr * 2 + 1]);
                    __half2 si = sig2(i2), sf = sig2(f2), so = sig2(o2), tg = tanh2(g2);
                    float2 fi = __half22float2(si), ff = __half22float2(sf), fg = __half22float2(tg);
                    float c0 = ff.x * cst[mt][t0][rr] + fi.x * fg.x;
                    float c1 = ff.y * cst[mt][t1][rr] + fi.y * fg.y;
                    cst[mt][t0][rr] = c0; cst[mt][t1][rr] = c1;
                    __half2 hh = __hmul2(so, tanh2(__floats2half2_rn(c0, c1)));
                    if (last) {
                        float2 hf = __half22float2(hh);
                        hvp[2 * p + 0] = hf.x;
                        hvp[2 * p + 1] = hf.y;
                    } else {
                        dst[p] = hh;
                    }
                }
                if (last) {
                    int node = base + row;
                    if (node < N)
                        *(float4*)(hb + (size_t)node * 64 + nj * 16 + q * 4) = hv4;
                }
            }
        }
    }
}

// ---------------- SAGE output: out = relu([A1 || A2] * Wo^T + b), split fp16 ------
template<int KOUT>
__global__ __launch_bounds__(256, 1)
void sage_linear(const float* __restrict__ A1,   // [N,64] root feats
                 const float* __restrict__ A2,   // [N,64] aggr h
                 const __half* __restrict__ Whi, const __half* __restrict__ Wlo,
                 const float* __restrict__ bias, float* __restrict__ out, int N) {
    constexpr int NT = KOUT / 32;
    extern __shared__ __half sh[];
    __half* s_wh = sh;                         // KOUT*KH128
    __half* s_wl = s_wh + KOUT * KH128;
    __half* s_ah = s_wl + KOUT * KH128;        // 128*KH128
    __half* s_al = s_ah + 128 * KH128;
    float*  s_b  = (float*)(s_al + 128 * KH128);

    const int tx = threadIdx.x, base = blockIdx.x * 128;
    const int lane = tx & 31, w = tx >> 5;
    const int mg = w >> 2, nj = w & 3;
    const int r = lane >> 2, q = lane & 3;
    const int mrow = mg * 64, nwb = nj * (KOUT / 4);

    for (int i = tx; i < KOUT * 16; i += 256) {
        int row = i >> 4, c = i & 15;
        ((uint4*)(s_wh + row * KH128))[c] = ((const uint4*)Whi)[i];
        ((uint4*)(s_wl + row * KH128))[c] = ((const uint4*)Wlo)[i];
    }
    for (int i = tx; i < KOUT; i += 256) s_b[i] = bias[i];
    for (int i = tx; i < 128 * 32; i += 256) {
        int n = i >> 5, c = i & 31;
        int node = base + n;
        float4 v = make_float4(0.f, 0.f, 0.f, 0.f);
        if (node < N)
            v = (c < 16) ? ((const float4*)(A1 + (size_t)node * 64))[c]
                         : ((const float4*)(A2 + (size_t)node * 64))[c - 16];
        __half2 h0 = __floats2half2_rn(v.x, v.y), h1 = __floats2half2_rn(v.z, v.w);
        float2 f0 = __half22float2(h0), f1 = __half22float2(h1);
        __half2* dh = (__half2*)(s_ah + n * KH128 + c * 4);
        __half2* dl = (__half2*)(s_al + n * KH128 + c * 4);
        dh[0] = h0; dh[1] = h1;
        dl[0] = __floats2half2_rn(v.x - f0.x, v.y - f0.y);
        dl[1] = __floats2half2_rn(v.z - f1.x, v.w - f1.y);
    }
    __syncthreads();

    float acc[4][NT][4];
    #pragma unroll
    for (int mt = 0; mt < 4; mt++)
        #pragma unroll
        for (int nt = 0; nt < NT; nt++) {
            int c0 = nwb + nt * 8 + 2 * q;
            acc[mt][nt][0] = s_b[c0];     acc[mt][nt][1] = s_b[c0 + 1];
            acc[mt][nt][2] = s_b[c0];     acc[mt][nt][3] = s_b[c0 + 1];
        }
    #pragma unroll 2
    for (int kc = 0; kc < 8; kc++) {
        const int kw = kc * 8;
        uint32_t ah[4][4], al[4][4];
        #pragma unroll
        for (int mt = 0; mt < 4; mt++) {
            const uint32_t* ap = (const uint32_t*)s_ah + (mrow + mt * 16 + r) * WS128 + kw + q;
            const uint32_t* lp = (const uint32_t*)s_al + (mrow + mt * 16 + r) * WS128 + kw + q;
            ah[mt][0] = ap[0]; ah[mt][1] = ap[8 * WS128]; ah[mt][2] = ap[4]; ah[mt][3] = ap[8 * WS128 + 4];
            al[mt][0] = lp[0]; al[mt][1] = lp[8 * WS128]; al[mt][2] = lp[4]; al[mt][3] = lp[8 * WS128 + 4];
        }
        #pragma unroll
        for (int nt = 0; nt < NT; nt++) {
            const uint32_t* bh = (const uint32_t*)s_wh + (nwb + nt * 8 + r) * WS128 + kw + q;
            const uint32_t* bl = (const uint32_t*)s_wl + (nwb + nt * 8 + r) * WS128 + kw + q;
            uint32_t bh0 = bh[0], bh1 = bh[4], bl0 = bl[0], bl1 = bl[4];
            #pragma unroll
            for (int mt = 0; mt < 4; mt++) {
                MMA_F16(acc[mt][nt], ah[mt], bh0, bh1);
                MMA_F16(acc[mt][nt], ah[mt], bl0, bl1);
                MMA_F16(acc[mt][nt], al[mt], bh0, bh1);
            }
        }
    }
    #pragma unroll
    for (int mt = 0; mt < 4; mt++)
        #pragma unroll
        for (int nt = 0; nt < NT; nt++)
            #pragma unroll
            for (int rr = 0; rr < 2; rr++) {
                int node = base + mrow + mt * 16 + r + 8 * rr;
                if (node < N) {
                    int c0 = nwb + nt * 8 + 2 * q;
                    float2 v;
                    v.x = fmaxf(acc[mt][nt][2 * rr + 0], 0.f);
                    v.y = fmaxf(acc[mt][nt][2 * rr + 1], 0.f);
                    *(float2*)(out + (size_t)node * KOUT + c0) = v;
                }
            }
}

// ---------------- split-fp16 MMA linear + relu ----------------
template<int KIN, int KOUT, bool HOUT>
__global__ __launch_bounds__(256, 1)
void mma_linear(const float* __restrict__ A,
                const __half* __restrict__ Whi, const __half* __restrict__ Wlo,
                const float* __restrict__ bias, void* __restrict__ outp, int N) {
    constexpr int KH = KIN + 8, WSL = KH / 2, CH = KIN / 16;
    constexpr int NT = KOUT / 32;
    extern __shared__ __half sh[];
    __half* s_wh = sh;
    __half* s_wl = s_wh + KOUT * KH;
    __half* s_ah = s_wl + KOUT * KH;
    __half* s_al = s_ah + 128 * KH;
    float*  s_b  = (float*)(s_al + 128 * KH);

    const int tx = threadIdx.x, base = blockIdx.x * 128;
    const int lane = tx & 31, w = tx >> 5;
    const int mg = w >> 2, nj = w & 3;
    const int r = lane >> 2, q = lane & 3;
    const int mrow = mg * 64, nwb = nj * (KOUT / 4);

    for (int i = tx; i < KOUT * (KIN / 8); i += 256) {
        int row = i / (KIN / 8), c = i % (KIN / 8);
        ((uint4*)(s_wh + row * KH))[c] = ((const uint4*)Whi)[i];
        ((uint4*)(s_wl + row * KH))[c] = ((const uint4*)Wlo)[i];
    }
    for (int i = tx; i < KOUT; i += 256) s_b[i] = bias[i];
    for (int i = tx; i < 128 * (KIN / 4); i += 256) {
        int n = i / (KIN / 4), c = i % (KIN / 4);
        int node = base + n;
        float4 v = make_float4(0.f, 0.f, 0.f, 0.f);
        if (node < N) v = ((const float4*)(A + (size_t)node * KIN))[c];
        __half2 h0 = __floats2half2_rn(v.x, v.y), h1 = __floats2half2_rn(v.z, v.w);
        float2 f0 = __half22float2(h0), f1 = __half22float2(h1);
        __half2* dh = (__half2*)(s_ah + n * KH + c * 4);
        __half2* dl = (__half2*)(s_al + n * KH + c * 4);
        dh[0] = h0; dh[1] = h1;
        dl[0] = __floats2half2_rn(v.x - f0.x, v.y - f0.y);
        dl[1] = __floats2half2_rn(v.z - f1.x, v.w - f1.y);
    }
    __syncthreads();

    float acc[4][NT][4];
    #pragma unroll
    for (int mt = 0; mt < 4; mt++)
        #pragma unroll
        for (int nt = 0; nt < NT; nt++) {
            int c0 = nwb + nt * 8 + 2 * q;
            acc[mt][nt][0] = s_b[c0];     acc[mt][nt][1] = s_b[c0 + 1];
            acc[mt][nt][2] = s_b[c0];     acc[mt][nt][3] = s_b[c0 + 1];
        }
    #pragma unroll 2
    for (int kc = 0; kc < CH; kc++) {
        const int kw = kc * 8;
        uint32_t ah[4][4], al[4][4];
        #pragma unroll
        for (int mt = 0; mt < 4; mt++) {
            const uint32_t* ap = (const uint32_t*)s_ah + (mrow + mt * 16 + r) * WSL + kw + q;
            const uint32_t* lp = (const uint32_t*)s_al + (mrow + mt * 16 + r) * WSL + kw + q;
            ah[mt][0] = ap[0]; ah[mt][1] = ap[8 * WSL]; ah[mt][2] = ap[4]; ah[mt][3] = ap[8 * WSL + 4];
            al[mt][0] = lp[0]; al[mt][1] = lp[8 * WSL]; al[mt][2] = lp[4]; al[mt][3] = lp[8 * WSL + 4];
        }
        #pragma unroll
        for (int nt = 0; nt < NT; nt++) {
            const uint32_t* bh = (const uint32_t*)s_wh + (nwb + nt * 8 + r) * WSL + kw + q;
            const uint32_t* bl = (const uint32_t*)s_wl + (nwb + nt * 8 + r) * WSL + kw + q;
            uint32_t bh0 = bh[0], bh1 = bh[4], bl0 = bl[0], bl1 = bl[4];
            #pragma unroll
            for (int mt = 0; mt < 4; mt++) {
                MMA_F16(acc[mt][nt], ah[mt], bh0, bh1);
                MMA_F16(acc[mt][nt], ah[mt], bl0, bl1);
                MMA_F16(acc[mt][nt], al[mt], bh0, bh1);
            }
        }
    }
    #pragma unroll
    for (int mt = 0; mt < 4; mt++)
        #pragma unroll
        for (int nt = 0; nt < NT; nt++)
            #pragma unroll
            for (int rr = 0; rr < 2; rr++) {
                int node = base + mrow + mt * 16 + r + 8 * rr;
                if (node < N) {
                    int c0 = nwb + nt * 8 + 2 * q;
                    float vx = fmaxf(acc[mt][nt][2 * rr + 0], 0.f);
                    float vy = fmaxf(acc[mt][nt][2 * rr + 1], 0.f);
                    if (HOUT) {
                        *(__half2*)((__half*)outp + (size_t)node * KOUT + c0) =
                            __floats2half2_rn(vx, vy);
                    } else {
                        *(float2*)((float*)outp + (size_t)node * KOUT + c0) =
                            make_float2(vx, vy);
                    }
                }
            }
}

// ---------------- host launcher ----------------
static void* symaddr(const void* sym) {
    void* p = nullptr;
    cudaGetSymbolAddress(&p, sym);
    return p;
}

extern "C" void kernel_launch(void* const* d_in, const int* in_sizes, int n_in,
                              void* d_out, int out_size) {
    const float* x   = (const float*)d_in[0];
    const int*   ei  = (const int*)d_in[1];
    const int N = in_sizes[0] / 64;
    const int E = in_sizes[1] / 2;
    const int* src = ei;

    const float* p1pw  = (const float*)d_in[3];
    const float* p1pb  = (const float*)d_in[4];
    const float* p1wih = (const float*)d_in[5];
    const float* p1whh = (const float*)d_in[6];
    const float* p1bih = (const float*)d_in[7];
    const float* p1bhh = (const float*)d_in[8];
    const float* p1llw = (const float*)d_in[9];
    const float* p1llb = (const float*)d_in[10];
    const float* p1lrw = (const float*)d_in[11];
    const float* p2pw  = (const float*)d_in[12];
    const float* p2pb  = (const float*)d_in[13];
    const float* p2wih = (const float*)d_in[14];
    const float* p2whh = (const float*)d_in[15];
    const float* p2bih = (const float*)d_in[16];
    const float* p2bhh = (const float*)d_in[17];
    const float* p2llw = (const float*)d_in[18];
    const float* p2llb = (const float*)d_in[19];
    const float* p2lrw = (const float*)d_in[20];
    const float* l1w   = (const float*)d_in[21];
    const float* l1b   = (const float*)d_in[22];
    const float* l2w   = (const float*)d_in[23];
    const float* l2b   = (const float*)d_in[24];
    const float* l3w   = (const float*)d_in[25];
    const float* l3b   = (const float*)d_in[26];

    __half* xp  = (__half*)symaddr(g_xp);
    __half* xg  = (__half*)symaddr(g_xg);
    float*  hb  = (float*)symaddr(g_hb);
    float*  h1  = (float*)symaddr(g_h1);
    float*  h2  = (float*)symaddr(g_h2);
    float*  t1  = (float*)symaddr(g_t1);
    float*  t2  = (float*)symaddr(g_t2);
    __half* wx1 = (__half*)symaddr(g_wx1);
    __half* wh1 = (__half*)symaddr(g_wh1);
    __half* wx2 = (__half*)symaddr(g_wx2);
    __half* wh2 = (__half*)symaddr(g_wh2);
    float*  bs1 = (float*)symaddr(g_bs1);
    float*  bs2 = (float*)symaddr(g_bs2);
    __half* wo1h = (__half*)symaddr(g_wo1h); __half* wo1l = (__half*)symaddr(g_wo1l);
    __half* wo2h = (__half*)symaddr(g_wo2h); __half* wo2l = (__half*)symaddr(g_wo2l);
    __half* pT1h = (__half*)symaddr(g_pT1h); __half* pT1l = (__half*)symaddr(g_pT1l);
    __half* pT2h = (__half*)symaddr(g_pT2h); __half* pT2l = (__half*)symaddr(g_pT2l);
    __half* l1h  = (__half*)symaddr(g_l1h);  __half* l1l  = (__half*)symaddr(g_l1l);
    __half* l2h  = (__half*)symaddr(g_l2h);  __half* l2l  = (__half*)symaddr(g_l2l);
    __half* l3h  = (__half*)symaddr(g_l3h);  __half* l3l  = (__half*)symaddr(g_l3l);

    // smem sizes
    const int SM_REC  = 23040 * 2 + 512 * 4;                                     // 48128
    const int SM_XG   = (256 * KHW + 64 * KHW) * 2 + 256 * 4;                    // 47104
    const int SM_SAGE64  = (2 * 64 * KH128 + 2 * 128 * KH128) * 2 + 64 * 4;      // 104704
    const int SM_SAGE128 = (2 * 128 * KH128 + 2 * 128 * KH128) * 2 + 128 * 4;    // 139776
    const int SM_6464 = (2 * 64 * 72 + 2 * 128 * 72) * 2 + 64 * 4;               // 55552
    const int SM_L1   = (2 * 192 * 136 + 2 * 128 * 136) * 2 + 192 * 4;           // 174848
    const int SM_L2   = (2 * 64 * 200 + 2 * 128 * 200) * 2 + 64 * 4;             // 153856
    cudaFuncSetAttribute(lstm_rec,                   cudaFuncAttributeMaxDynamicSharedMemorySize, SM_REC);
    cudaFuncSetAttribute(xg_kernel,                  cudaFuncAttributeMaxDynamicSharedMemorySize, SM_XG);
    cudaFuncSetAttribute(sage_linear<64>,            cudaFuncAttributeMaxDynamicSharedMemorySize, SM_SAGE64);
    cudaFuncSetAttribute(sage_linear<128>,           cudaFuncAttributeMaxDynamicSharedMemorySize, SM_SAGE128);
    cudaFuncSetAttribute(mma_linear<64, 64, true>,   cudaFuncAttributeMaxDynamicSharedMemorySize, SM_6464);
    cudaFuncSetAttribute(mma_linear<128, 192, false>, cudaFuncAttributeMaxDynamicSharedMemorySize, SM_L1);
    cudaFuncSetAttribute(mma_linear<192, 64, false>, cudaFuncAttributeMaxDynamicSharedMemorySize, SM_L2);
    cudaFuncSetAttribute(mma_linear<64, 64, false>,  cudaFuncAttributeMaxDynamicSharedMemorySize, SM_6464);

    // --- fused weight prep ---
    k_prep_all<<<544, 256>>>(p1wih, p1whh, p1bih, p1bhh,
                             p2wih, p2whh, p2bih, p2bhh,
                             p1llw, p1lrw, p2llw, p2lrw,
                             p1pw, p2pw, l1w, l2w, l3w);

    const int NB128 = (N + 127) / 128;
    const int NB64  = (N + 63) / 64;
    const int NB32  = (N + 31) / 32;

    // --- layer 1 ---
    mma_linear<64, 64, true><<<NB128, 256, SM_6464>>>(x, pT1h, pT1l, p1pb, xp, N);
    xg_kernel<<<NB64, 256, SM_XG>>>(xp, wx1, bs1, xg, N);
    lstm_rec<<<NB32, 128, SM_REC>>>(xg, src, wh1, hb, N);
    sage_linear<64><<<NB128, 256, SM_SAGE64>>>(x, hb, wo1h, wo1l, p1llb, h1, N);
    // --- layer 2 ---
    mma_linear<64, 64, true><<<NB128, 256, SM_6464>>>(h1, pT2h, pT2l, p2pb, xp, N);
    xg_kernel<<<NB64, 256, SM_XG>>>(xp, wx2, bs2, xg, N);
    lstm_rec<<<NB32, 128, SM_REC>>>(xg, src, wh2, hb, N);
    sage_linear<128><<<NB128, 256, SM_SAGE128>>>(h1, hb, wo2h, wo2l, p2llb, h2, N);
    // --- MLP head ---
    mma_linear<128, 192, false><<<NB128, 256, SM_L1>>>(h2, l1h, l1l, l1b, t1, N);
    mma_linear<192, 64, false><<<NB128, 256, SM_L2>>>(t1, l2h, l2l, l2b, t2, N);
    mma_linear<64, 64, false><<<NB128, 256, SM_6464>>>(t2, l3h, l3l, l3b, (float*)d_out, N);

    // --- edge_index passthrough if the output buffer holds it ---
    long hsz = (long)N * 64;
    if ((long)out_size > hsz) {
        long remaining = (long)out_size - hsz;
        int count = (int)((remaining < (long)2 * E) ? remaining : (long)2 * E);
        k_edge_copy<<<(count + 255) / 256, 256>>>(ei, (float*)d_out + hsz, count);
    }
}

// round 16
// speedup vs baseline: 1.2840x; 1.0349x over previous
#include <cuda_runtime.h>
#include <cuda_fp16.h>
#include <cstdint>

// Problem constants (fixed-shape problem)
#define MAXN 50000
#define KDEG 16

#define KHW   72     // W / h / xp row stride in halves (64 + 8 pad) -> conflict-free
#define KH128 136    // [x||h] row stride in halves
#define WS128 68     // word stride of KH128

// ---------------- scratch (device globals: allocation-free) ----------------
__device__ __half g_xg [MAXN * 256];    // Wx*relu(proj(x)) + b, fragment-ordered, fp16
__device__ float  g_hb [MAXN * 64];     // LSTM final h, fp32
__device__ float  g_h1 [MAXN * 64];
__device__ float  g_h2 [MAXN * 128];
__device__ float  g_t1 [MAXN * 192];
__device__ float  g_t2 [MAXN * 64];

__device__ __half g_wx1 [256 * 64];     // permuted Wx [pcol][k]
__device__ __half g_wh1 [256 * 64];     // permuted Wh [pcol][k]
__device__ __half g_wx2 [256 * 64];
__device__ __half g_wh2 [256 * 64];
__device__ float  g_bs1 [256];          // permuted bih+bhh
__device__ float  g_bs2 [256];
__device__ __half g_wo1h[64 * 128],  g_wo1l[64 * 128];
__device__ __half g_wo2h[128 * 128], g_wo2l[128 * 128];
__device__ __half g_pT1h[64 * 64],   g_pT1l[64 * 64];
__device__ __half g_pT2h[64 * 64],   g_pT2l[64 * 64];
__device__ __half g_l1h [192 * 128], g_l1l [192 * 128];
__device__ __half g_l2h [64 * 192],  g_l2l [64 * 192];
__device__ __half g_l3h [64 * 64],   g_l3l [64 * 64];

// ---------------- helpers ----------------
__device__ __forceinline__ __half2 tanh2(__half2 x) {
    __half2 y;
    asm("tanh.approx.f16x2 %0, %1;" : "=r"(*(uint32_t*)&y) : "r"(*(const uint32_t*)&x));
    return y;
}
__device__ __forceinline__ __half2 sig2(__half2 x) {
    const __half2 h05 = __float2half2_rn(0.5f);
    return __hfma2(tanh2(__hmul2(x, h05)), h05, h05);
}

#define MMA_F16(D, A, b0, b1)                                                   \
    asm volatile("mma.sync.aligned.m16n8k16.row.col.f32.f16.f16.f32 "           \
                 "{%0,%1,%2,%3}, {%4,%5,%6,%7}, {%8,%9}, {%0,%1,%2,%3};"        \
                 : "+f"(D[0]), "+f"(D[1]), "+f"(D[2]), "+f"(D[3])               \
                 : "r"(A[0]), "r"(A[1]), "r"(A[2]), "r"(A[3]), "r"(b0), "r"(b1));

#define LDSM_X4(R, addr)                                                        \
    asm volatile("ldmatrix.sync.aligned.m8n8.x4.shared.b16 {%0,%1,%2,%3}, [%4];"\
                 : "=r"((R)[0]), "=r"((R)[1]), "=r"((R)[2]), "=r"((R)[3])       \
                 : "r"(addr));

// Gate-column permutation: each thread's accumulator fragment owns the full
// (i,f,g,o) quadruple for its hidden units.
__device__ __forceinline__ int perm_orig_col(int p) {
    int nj = p >> 6, rr = p & 63;
    int tp = rr >> 4, r2 = rr & 15;
    int half_ = r2 >> 3, r3 = r2 & 7;
    int q = r3 >> 1, low = r3 & 1;
    int gate = half_ * 2 + low;             // 0=i 1=f 2=g 3=o
    int jg = nj * 16 + q * 4 + tp;
    return gate * 64 + jg;
}

__device__ __forceinline__ void wsplit(__half* hi, __half* lo, int idx, float v) {
    __half h = __float2half_rn(v);
    hi[idx] = h;
    lo[idx] = __float2half_rn(v - __half2float(h));
}

// ---------------- single fused prep kernel ----------------
__global__ void k_prep_all(
    const float* p1wih, const float* p1whh, const float* p1bih, const float* p1bhh,
    const float* p2wih, const float* p2whh, const float* p2bih, const float* p2bhh,
    const float* p1llw, const float* p1lrw, const float* p2llw, const float* p2lrw,
    const float* p1pw, const float* p2pw,
    const float* l1w, const float* l2w, const float* l3w) {
    int b = blockIdx.x, t = threadIdx.x;
    if (b < 64) {                        // wx1: 256x64
        int idx = b * 256 + t;
        int p = idx >> 6, k = idx & 63;
        g_wx1[idx] = __float2half_rn(p1wih[perm_orig_col(p) * 64 + k]);
        if (idx < 256) { int g2 = perm_orig_col(idx); g_bs1[idx] = p1bih[g2] + p1bhh[g2]; }
    } else if (b < 128) {                // wh1
        int idx = (b - 64) * 256 + t;
        int p = idx >> 6, k = idx & 63;
        g_wh1[idx] = __float2half_rn(p1whh[perm_orig_col(p) * 64 + k]);
    } else if (b < 192) {                // wx2
        int idx = (b - 128) * 256 + t;
        int p = idx >> 6, k = idx & 63;
        g_wx2[idx] = __float2half_rn(p2wih[perm_orig_col(p) * 64 + k]);
        if (idx < 256) { int g2 = perm_orig_col(idx); g_bs2[idx] = p2bih[g2] + p2bhh[g2]; }
    } else if (b < 256) {                // wh2
        int idx = (b - 192) * 256 + t;
        int p = idx >> 6, k = idx & 63;
        g_wh2[idx] = __float2half_rn(p2whh[perm_orig_col(p) * 64 + k]);
    } else if (b < 288) {                // wo1: 64x128
        int idx = (b - 256) * 256 + t;
        int o = idx >> 7, k = idx & 127;
        wsplit(g_wo1h, g_wo1l, idx, k < 64 ? p1lrw[o * 64 + k] : p1llw[o * 64 + (k - 64)]);
    } else if (b < 352) {                // wo2: 128x128
        int idx = (b - 288) * 256 + t;
        int o = idx >> 7, k = idx & 127;
        wsplit(g_wo2h, g_wo2l, idx, k < 64 ? p2lrw[o * 64 + k] : p2llw[o * 64 + (k - 64)]);
    } else if (b < 368) {                // pT1
        int idx = (b - 352) * 256 + t;
        wsplit(g_pT1h, g_pT1l, idx, p1pw[idx]);
    } else if (b < 384) {                // pT2
        int idx = (b - 368) * 256 + t;
        wsplit(g_pT2h, g_pT2l, idx, p2pw[idx]);
    } else if (b < 480) {                // l1
        int idx = (b - 384) * 256 + t;
        wsplit(g_l1h, g_l1l, idx, l1w[idx]);
    } else if (b < 528) {                // l2
        int idx = (b - 480) * 256 + t;
        wsplit(g_l2h, g_l2l, idx, l2w[idx]);
    } else {                             // l3
        int idx = (b - 528) * 256 + t;
        wsplit(g_l3h, g_l3l, idx, l3w[idx]);
    }
}

__global__ void k_edge_copy(const int* __restrict__ ei, float* __restrict__ out, int count) {
    int i = blockIdx.x * blockDim.x + threadIdx.x;
    if (i < count) out[i] = (float)ei[i];
}

// ---------------- fused proj+relu+xg kernel ----------------
// Phase 1: xp = relu(Wp·A + pb)  (split-fp16, 64x64 K=64) -> fp16 in smem
// Phase 2: xg = Wx(perm)·xp + gb (fp16, 64x256 K=64) -> fragment-ordered global
__global__ __launch_bounds__(256, 2)
void xpg_kernel(const float* __restrict__ A,
                const __half* __restrict__ Wph, const __half* __restrict__ Wpl,
                const float* __restrict__ pb,
                const __half* __restrict__ wx, const float* __restrict__ gb,
                __half* __restrict__ xg, int N) {
    extern __shared__ __half sh[];
    __half* s_wx  = sh;                         // 256*KHW = 18432
    __half* s_wph = sh + 18432;                 // 64*KHW = 4608
    __half* s_wpl = s_wph + 4608;
    __half* s_ah  = s_wpl + 4608;               // A hi plane; reused as xp
    __half* s_al  = s_ah + 4608;                // A lo plane
    float*  s_pb  = (float*)(s_al + 4608);      // 64
    float*  s_gb  = s_pb + 64;                  // 256

    const int tx = threadIdx.x, base = blockIdx.x * 64;
    const int lane = tx & 31, w = tx >> 5;
    const int mg = w >> 2, nj = w & 3;
    const int mrow = mg * 32;
    const int r = lane >> 2, q = lane & 3;
    const int tile = lane >> 3, lrow = lane & 7;

    // loads
    for (int i = tx; i < 2048; i += 256) {              // wx: 256 rows * 8 uint4
        int row = i >> 3, c = i & 7;
        ((uint4*)(s_wx + row * KHW))[c] = ((const uint4*)wx)[i];
    }
    for (int i = tx; i < 512; i += 256) {               // wp hi/lo: 64 rows * 8 uint4
        int row = i >> 3, c = i & 7;
        ((uint4*)(s_wph + row * KHW))[c] = ((const uint4*)Wph)[i];
        ((uint4*)(s_wpl + row * KHW))[c] = ((const uint4*)Wpl)[i];
    }
    if (tx < 64) s_pb[tx] = pb[tx];
    s_gb[tx] = gb[tx];
    for (int i = tx; i < 1024; i += 256) {              // A: 64 rows * 16 float4
        int row = i >> 4, c = i & 15;
        int node = base + row;
        float4 v = make_float4(0.f, 0.f, 0.f, 0.f);
        if (node < N) v = ((const float4*)(A + (size_t)node * 64))[c];
        __half2 h0 = __floats2half2_rn(v.x, v.y), h1 = __floats2half2_rn(v.z, v.w);
        float2 f0 = __half22float2(h0), f1 = __half22float2(h1);
        __half2* dh = (__half2*)(s_ah + row * KHW + c * 4);
        __half2* dl = (__half2*)(s_al + row * KHW + c * 4);
        dh[0] = h0; dh[1] = h1;
        dl[0] = __floats2half2_rn(v.x - f0.x, v.y - f0.y);
        dl[1] = __floats2half2_rn(v.z - f1.x, v.w - f1.y);
    }
    __syncthreads();

    const uint32_t s_ah_u  = (uint32_t)__cvta_generic_to_shared(s_ah);
    const uint32_t s_al_u  = (uint32_t)__cvta_generic_to_shared(s_al);
    const uint32_t s_wph_u = (uint32_t)__cvta_generic_to_shared(s_wph);
    const uint32_t s_wpl_u = (uint32_t)__cvta_generic_to_shared(s_wpl);
    const uint32_t s_wx_u  = (uint32_t)__cvta_generic_to_shared(s_wx);

    uint32_t aoff[2];
    #pragma unroll
    for (int mt = 0; mt < 2; mt++)
        aoff[mt] = 2 * ((mrow + mt * 16 + (tile & 1) * 8 + lrow) * KHW + (tile >> 1) * 8);
    const uint32_t bpoff = 2 * ((nj * 16 + (tile >> 1) * 8 + lrow) * KHW + (tile & 1) * 8);

    // ---- phase 1: proj GEMM (split fp16) ----
    float pacc[2][2][4];
    #pragma unroll
    for (int mt = 0; mt < 2; mt++)
        #pragma unroll
        for (int nt = 0; nt < 2; nt++) {
            int c0 = nj * 16 + nt * 8 + 2 * q;
            pacc[mt][nt][0] = s_pb[c0];     pacc[mt][nt][1] = s_pb[c0 + 1];
            pacc[mt][nt][2] = s_pb[c0];     pacc[mt][nt][3] = s_pb[c0 + 1];
        }
    #pragma unroll
    for (int kc = 0; kc < 4; kc++) {
        const uint32_t ko = kc * 32;
        uint32_t ah[2][4], al[2][4], bh[4], bl[4];
        LDSM_X4(ah[0], s_ah_u + aoff[0] + ko);
        LDSM_X4(ah[1], s_ah_u + aoff[1] + ko);
        LDSM_X4(al[0], s_al_u + aoff[0] + ko);
        LDSM_X4(al[1], s_al_u + aoff[1] + ko);
        LDSM_X4(bh, s_wph_u + bpoff + ko);
        LDSM_X4(bl, s_wpl_u + bpoff + ko);
        #pragma unroll
        for (int mt = 0; mt < 2; mt++) {
            MMA_F16(pacc[mt][0], ah[mt], bh[0], bh[1]);
            MMA_F16(pacc[mt][0], ah[mt], bl[0], bl[1]);
            MMA_F16(pacc[mt][0], al[mt], bh[0], bh[1]);
            MMA_F16(pacc[mt][1], ah[mt], bh[2], bh[3]);
            MMA_F16(pacc[mt][1], ah[mt], bl[2], bl[3]);
            MMA_F16(pacc[mt][1], al[mt], bh[2], bh[3]);
        }
    }
    __syncthreads();   // all phase-1 reads of s_ah/s_al done

    // write xp = relu(pacc) as fp16 into s_ah (reused as xp plane)
    #pragma unroll
    for (int mt = 0; mt < 2; mt++)
        #pragma unroll
        for (int nt = 0; nt < 2; nt++)
            #pragma unroll
            for (int rr = 0; rr < 2; rr++) {
                int row = mrow + mt * 16 + r + 8 * rr;
                int col = nj * 16 + nt * 8 + 2 * q;
                float vx = fmaxf(pacc[mt][nt][2 * rr + 0], 0.f);
                float vy = fmaxf(pacc[mt][nt][2 * rr + 1], 0.f);
                *(__half2*)(s_ah + row * KHW + col) = __floats2half2_rn(vx, vy);
            }
    __syncthreads();

    // ---- phase 2: xg GEMM ----
    const int nwb = nj * 64;
    uint32_t baddr[4];
    #pragma unroll
    for (int np = 0; np < 4; np++)
        baddr[np] = s_wx_u + 2 * ((nwb + np * 16 + (tile >> 1) * 8 + lrow) * KHW + (tile & 1) * 8);

    float acc[2][8][4];
    #pragma unroll
    for (int mt = 0; mt < 2; mt++)
        #pragma unroll
        for (int nt = 0; nt < 8; nt++) {
            float b0 = s_gb[nwb + nt * 8 + 2 * q], b1 = s_gb[nwb + nt * 8 + 2 * q + 1];
            acc[mt][nt][0] = b0; acc[mt][nt][1] = b1;
            acc[mt][nt][2] = b0; acc[mt][nt][3] = b1;
        }
    #pragma unroll
    for (int kc = 0; kc < 4; kc++) {
        const uint32_t ko = kc * 32;
        uint32_t af[2][4];
        LDSM_X4(af[0], s_ah_u + aoff[0] + ko);
        LDSM_X4(af[1], s_ah_u + aoff[1] + ko);
        #pragma unroll
        for (int np = 0; np < 4; np++) {
            uint32_t bf[4];
            LDSM_X4(bf, baddr[np] + ko);
            MMA_F16(acc[0][2 * np],     af[0], bf[0], bf[1]);
            MMA_F16(acc[1][2 * np],     af[1], bf[0], bf[1]);
            MMA_F16(acc[0][2 * np + 1], af[0], bf[2], bf[3]);
            MMA_F16(acc[1][2 * np + 1], af[1], bf[2], bf[3]);
        }
    }
    const int gpos = (nj * 4 + q) << 4;
    #pragma unroll
    for (int mt = 0; mt < 2; mt++)
        #pragma unroll
        for (int rr = 0; rr < 2; rr++) {
            int node = base + mrow + mt * 16 + r + 8 * rr;
            if (node < N) {
                uint32_t hv[8];
                #pragma unroll
                for (int nt = 0; nt < 8; nt++) {
                    __half2 h = __floats2half2_rn(acc[mt][nt][rr * 2 + 0], acc[mt][nt][rr * 2 + 1]);
                    hv[nt] = *(uint32_t*)&h;
                }
                uint4* dst = (uint4*)(xg + (size_t)node * 256 + gpos);
                dst[0] = make_uint4(hv[0], hv[1], hv[2], hv[3]);
                dst[1] = make_uint4(hv[4], hv[5], hv[6], hv[7]);
            }
        }
}

// ---------------- LSTM recurrence only (32 nodes/block, 4 CTA/SM) ----------------
__global__ __launch_bounds__(128, 4)
void lstm_rec(const __half* __restrict__ xg,
              const int*    __restrict__ src,
              const __half* __restrict__ whc,    // [256][64] permuted
              float* __restrict__ hb,            // [N,64] fp32 out
              int N) {
    extern __shared__ __half smh[];
    __half* s_wh = smh;                          // 256*KHW = 18432 halves
    __half* s_h0 = smh + 18432;                  // 32*KHW = 2304
    __half* s_h1 = smh + 20736;                  // 2304
    int*    s_src = (int*)(smh + 23040);         // 512 ints

    const int tx = threadIdx.x;
    const int base = blockIdx.x * 32;
    const int lane = tx & 31, nj = tx >> 5;
    const int nwb = nj * 64;
    const int r = lane >> 2, q = lane & 3;
    const int tile = lane >> 3, lrow = lane & 7;

    for (int i = tx; i < 2048; i += 128) {
        int row = i >> 3, c = i & 7;
        ((uint4*)(s_wh + row * KHW))[c] = ((const uint4*)whc)[i];
    }
    for (int i = tx; i < 512; i += 128) {
        int node = base + (i >> 4);
        s_src[i] = (node < N) ? src[node * KDEG + (i & 15)] : 0;
    }
    for (int i = tx; i < (32 * KHW) / 8; i += 128)
        ((uint4*)s_h0)[i] = make_uint4(0u, 0u, 0u, 0u);
    __syncthreads();

    float cst[2][4][2];
    #pragma unroll
    for (int a = 0; a < 2; a++)
        #pragma unroll
        for (int bb = 0; bb < 4; bb++) { cst[a][bb][0] = 0.f; cst[a][bb][1] = 0.f; }

    const uint32_t whu = (uint32_t)__cvta_generic_to_shared(s_wh);
    uint32_t hplane[2] = { (uint32_t)__cvta_generic_to_shared(s_h0),
                           (uint32_t)__cvta_generic_to_shared(s_h1) };
    uint32_t aoff[2], baddr[4];
    #pragma unroll
    for (int mt = 0; mt < 2; mt++)
        aoff[mt] = 2 * ((mt * 16 + (tile & 1) * 8 + lrow) * KHW + (tile >> 1) * 8);
    #pragma unroll
    for (int np = 0; np < 4; np++)
        baddr[np] = whu + 2 * ((nwb + np * 16 + (tile >> 1) * 8 + lrow) * KHW + (tile & 1) * 8);

    const int gpos = (nj * 4 + q) << 4;

    for (int t = 0; t < KDEG; t++) {
        __syncthreads();   // prior step's h visible

        // acc init: x-part (incl. bias) straight from L2 -> registers
        float acc[2][8][4];
        #pragma unroll
        for (int mt = 0; mt < 2; mt++)
            #pragma unroll
            for (int rr = 0; rr < 2; rr++) {
                int rowidx = mt * 16 + r + 8 * rr;
                int sn = s_src[rowidx * KDEG + t];
                const uint4* gp = (const uint4*)(xg + (size_t)sn * 256 + gpos);
                uint4 v0 = gp[0], v1 = gp[1];
                const uint32_t* pv = (const uint32_t*)&v0;
                #pragma unroll
                for (int j = 0; j < 4; j++) {
                    float2 f = __half22float2(*(const __half2*)&pv[j]);
                    acc[mt][j][rr * 2 + 0] = f.x;
                    acc[mt][j][rr * 2 + 1] = f.y;
                }
                const uint32_t* pw = (const uint32_t*)&v1;
                #pragma unroll
                for (int j = 0; j < 4; j++) {
                    float2 f = __half22float2(*(const __half2*)&pw[j]);
                    acc[mt][4 + j][rr * 2 + 0] = f.x;
                    acc[mt][4 + j][rr * 2 + 1] = f.y;
                }
            }

        // recurrent GEMM: += h_{t-1} @ Wh^T   (K = 64)
        const uint32_t hbse = hplane[t & 1];
        #pragma unroll
        for (int kc = 0; kc < 4; kc++) {
            const uint32_t ko = kc * 32;
            uint32_t af[2][4];
            LDSM_X4(af[0], hbse + aoff[0] + ko);
            LDSM_X4(af[1], hbse + aoff[1] + ko);
            #pragma unroll
            for (int np = 0; np < 4; np++) {
                uint32_t bf[4];
                LDSM_X4(bf, baddr[np] + ko);
                MMA_F16(acc[0][2 * np],     af[0], bf[0], bf[1]);
                MMA_F16(acc[1][2 * np],     af[1], bf[0], bf[1]);
                MMA_F16(acc[0][2 * np + 1], af[0], bf[2], bf[3]);
                MMA_F16(acc[1][2 * np + 1], af[1], bf[2], bf[3]);
            }
        }

        // activation: f16x2 tanh path, c-state fp32
        const bool last = (t == KDEG - 1);
        __half* hn = ((t + 1) & 1) ? s_h1 : s_h0;
        #pragma unroll
        for (int mt = 0; mt < 2; mt++) {
            #pragma unroll
            for (int rr = 0; rr < 2; rr++) {
                int row = mt * 16 + r + 8 * rr;
                __half2* dst = (__half2*)(hn + row * KHW + nj * 16 + q * 4);
                float4 hv4;
                float* hvp = (float*)&hv4;
                #pragma unroll
                for (int p = 0; p < 2; p++) {
                    int t0 = 2 * p, t1 = 2 * p + 1;
                    __half2 i2 = __floats2half2_rn(acc[mt][2 * t0][rr * 2 + 0], acc[mt][2 * t1][rr * 2 + 0]);
                    __half2 f2 = __floats2half2_rn(acc[mt][2 * t0][rr * 2 + 1], acc[mt][2 * t1][rr * 2 + 1]);
                    __half2 g2 = __floats2half2_rn(acc[mt][2 * t0 + 1][rr * 2 + 0], acc[mt][2 * t1 + 1][rr * 2 + 0]);
                    __half2 o2 = __floats2half2_rn(acc[mt][2 * t0 + 1][rr * 2 + 1], acc[mt][2 * t1 + 1][rr * 2 + 1]);
                    __half2 si = sig2(i2), sf = sig2(f2), so = sig2(o2), tg = tanh2(g2);
                    float2 fi = __half22float2(si), ff = __half22float2(sf), fg = __half22float2(tg);
                    float c0 = ff.x * cst[mt][t0][rr] + fi.x * fg.x;
                    float c1 = ff.y * cst[mt][t1][rr] + fi.y * fg.y;
                    cst[mt][t0][rr] = c0; cst[mt][t1][rr] = c1;
                    __half2 hh = __hmul2(so, tanh2(__floats2half2_rn(c0, c1)));
                    if (last) {
                        float2 hf = __half22float2(hh);
                        hvp[2 * p + 0] = hf.x;
                        hvp[2 * p + 1] = hf.y;
                    } else {
                        dst[p] = hh;
                    }
                }
                if (last) {
                    int node = base + row;
                    if (node < N)
                        *(float4*)(hb + (size_t)node * 64 + nj * 16 + q * 4) = hv4;
                }
            }
        }
    }
}

// ---------------- SAGE output: out = relu([A1 || A2] * Wo^T + b), split fp16 ------
template<int KOUT>
__global__ __launch_bounds__(256, 1)
void sage_linear(const float* __restrict__ A1,
                 const float* __restrict__ A2,
                 const __half* __restrict__ Whi, const __half* __restrict__ Wlo,
                 const float* __restrict__ bias, float* __restrict__ out, int N) {
    constexpr int NT = KOUT / 32;
    extern __shared__ __half sh[];
    __half* s_wh = sh;
    __half* s_wl = s_wh + KOUT * KH128;
    __half* s_ah = s_wl + KOUT * KH128;
    __half* s_al = s_ah + 128 * KH128;
    float*  s_b  = (float*)(s_al + 128 * KH128);

    const int tx = threadIdx.x, base = blockIdx.x * 128;
    const int lane = tx & 31, w = tx >> 5;
    const int mg = w >> 2, nj = w & 3;
    const int r = lane >> 2, q = lane & 3;
    const int mrow = mg * 64, nwb = nj * (KOUT / 4);

    for (int i = tx; i < KOUT * 16; i += 256) {
        int row = i >> 4, c = i & 15;
        ((uint4*)(s_wh + row * KH128))[c] = ((const uint4*)Whi)[i];
        ((uint4*)(s_wl + row * KH128))[c] = ((const uint4*)Wlo)[i];
    }
    for (int i = tx; i < KOUT; i += 256) s_b[i] = bias[i];
    for (int i = tx; i < 128 * 32; i += 256) {
        int n = i >> 5, c = i & 31;
        int node = base + n;
        float4 v = make_float4(0.f, 0.f, 0.f, 0.f);
        if (node < N)
            v = (c < 16) ? ((const float4*)(A1 + (size_t)node * 64))[c]
                         : ((const float4*)(A2 + (size_t)node * 64))[c - 16];
        __half2 h0 = __floats2half2_rn(v.x, v.y), h1 = __floats2half2_rn(v.z, v.w);
        float2 f0 = __half22float2(h0), f1 = __half22float2(h1);
        __half2* dh = (__half2*)(s_ah + n * KH128 + c * 4);
        __half2* dl = (__half2*)(s_al + n * KH128 + c * 4);
        dh[0] = h0; dh[1] = h1;
        dl[0] = __floats2half2_rn(v.x - f0.x, v.y - f0.y);
        dl[1] = __floats2half2_rn(v.z - f1.x, v.w - f1.y);
    }
    __syncthreads();

    float acc[4][NT][4];
    #pragma unroll
    for (int mt = 0; mt < 4; mt++)
        #pragma unroll
        for (int nt = 0; nt < NT; nt++) {
            int c0 = nwb + nt * 8 + 2 * q;
            acc[mt][nt][0] = s_b[c0];     acc[mt][nt][1] = s_b[c0 + 1];
            acc[mt][nt][2] = s_b[c0];     acc[mt][nt][3] = s_b[c0 + 1];
        }
    #pragma unroll 2
    for (int kc = 0; kc < 8; kc++) {
        const int kw = kc * 8;
        uint32_t ah[4][4], al[4][4];
        #pragma unroll
        for (int mt = 0; mt < 4; mt++) {
            const uint32_t* ap = (const uint32_t*)s_ah + (mrow + mt * 16 + r) * WS128 + kw + q;
            const uint32_t* lp = (const uint32_t*)s_al + (mrow + mt * 16 + r) * WS128 + kw + q;
            ah[mt][0] = ap[0]; ah[mt][1] = ap[8 * WS128]; ah[mt][2] = ap[4]; ah[mt][3] = ap[8 * WS128 + 4];
            al[mt][0] = lp[0]; al[mt][1] = lp[8 * WS128]; al[mt][2] = lp[4]; al[mt][3] = lp[8 * WS128 + 4];
        }
        #pragma unroll
        for (int nt = 0; nt < NT; nt++) {
            const uint32_t* bh = (const uint32_t*)s_wh + (nwb + nt * 8 + r) * WS128 + kw + q;
            const uint32_t* bl = (const uint32_t*)s_wl + (nwb + nt * 8 + r) * WS128 + kw + q;
            uint32_t bh0 = bh[0], bh1 = bh[4], bl0 = bl[0], bl1 = bl[4];
            #pragma unroll
            for (int mt = 0; mt < 4; mt++) {
                MMA_F16(acc[mt][nt], ah[mt], bh0, bh1);
                MMA_F16(acc[mt][nt], ah[mt], bl0, bl1);
                MMA_F16(acc[mt][nt], al[mt], bh0, bh1);
            }
        }
    }
    #pragma unroll
    for (int mt = 0; mt < 4; mt++)
        #pragma unroll
        for (int nt = 0; nt < NT; nt++)
            #pragma unroll
            for (int rr = 0; rr < 2; rr++) {
                int node = base + mrow + mt * 16 + r + 8 * rr;
                if (node < N) {
                    int c0 = nwb + nt * 8 + 2 * q;
                    float2 v;
                    v.x = fmaxf(acc[mt][nt][2 * rr + 0], 0.f);
                    v.y = fmaxf(acc[mt][nt][2 * rr + 1], 0.f);
                    *(float2*)(out + (size_t)node * KOUT + c0) = v;
                }
            }
}

// ---------------- split-fp16 MMA linear + relu ----------------
template<int KIN, int KOUT>
__global__ __launch_bounds__(256, 1)
void mma_linear(const float* __restrict__ A,
                const __half* __restrict__ Whi, const __half* __restrict__ Wlo,
                const float* __restrict__ bias, float* __restrict__ outp, int N) {
    constexpr int KH = KIN + 8, WSL = KH / 2, CH = KIN / 16;
    constexpr int NT = KOUT / 32;
    extern __shared__ __half sh[];
    __half* s_wh = sh;
    __half* s_wl = s_wh + KOUT * KH;
    __half* s_ah = s_wl + KOUT * KH;
    __half* s_al = s_ah + 128 * KH;
    float*  s_b  = (float*)(s_al + 128 * KH);

    const int tx = threadIdx.x, base = blockIdx.x * 128;
    const int lane = tx & 31, w = tx >> 5;
    const int mg = w >> 2, nj = w & 3;
    const int r = lane >> 2, q = lane & 3;
    const int mrow = mg * 64, nwb = nj * (KOUT / 4);

    for (int i = tx; i < KOUT * (KIN / 8); i += 256) {
        int row = i / (KIN / 8), c = i % (KIN / 8);
        ((uint4*)(s_wh + row * KH))[c] = ((const uint4*)Whi)[i];
        ((uint4*)(s_wl + row * KH))[c] = ((const uint4*)Wlo)[i];
    }
    for (int i = tx; i < KOUT; i += 256) s_b[i] = bias[i];
    for (int i = tx; i < 128 * (KIN / 4); i += 256) {
        int n = i / (KIN / 4), c = i % (KIN / 4);
        int node = base + n;
        float4 v = make_float4(0.f, 0.f, 0.f, 0.f);
        if (node < N) v = ((const float4*)(A + (size_t)node * KIN))[c];
        __half2 h0 = __floats2half2_rn(v.x, v.y), h1 = __floats2half2_rn(v.z, v.w);
        float2 f0 = __half22float2(h0), f1 = __half22float2(h1);
        __half2* dh = (__half2*)(s_ah + n * KH + c * 4);
        __half2* dl = (__half2*)(s_al + n * KH + c * 4);
        dh[0] = h0; dh[1] = h1;
        dl[0] = __floats2half2_rn(v.x - f0.x, v.y - f0.y);
        dl[1] = __floats2half2_rn(v.z - f1.x, v.w - f1.y);
    }
    __syncthreads();

    float acc[4][NT][4];
    #pragma unroll
    for (int mt = 0; mt < 4; mt++)
        #pragma unroll
        for (int nt = 0; nt < NT; nt++) {
            int c0 = nwb + nt * 8 + 2 * q;
            acc[mt][nt][0] = s_b[c0];     acc[mt][nt][1] = s_b[c0 + 1];
            acc[mt][nt][2] = s_b[c0];     acc[mt][nt][3] = s_b[c0 + 1];
        }
    #pragma unroll 2
    for (int kc = 0; kc < CH; kc++) {
        const int kw = kc * 8;
        uint32_t ah[4][4], al[4][4];
        #pragma unroll
        for (int mt = 0; mt < 4; mt++) {
            const uint32_t* ap = (const uint32_t*)s_ah + (mrow + mt * 16 + r) * WSL + kw + q;
            const uint32_t* lp = (const uint32_t*)s_al + (mrow + mt * 16 + r) * WSL + kw + q;
            ah[mt][0] = ap[0]; ah[mt][1] = ap[8 * WSL]; ah[mt][2] = ap[4]; ah[mt][3] = ap[8 * WSL + 4];
            al[mt][0] = lp[0]; al[mt][1] = lp[8 * WSL]; al[mt][2] = lp[4]; al[mt][3] = lp[8 * WSL + 4];
        }
        #pragma unroll
        for (int nt = 0; nt < NT; nt++) {
            const uint32_t* bh = (const uint32_t*)s_wh + (nwb + nt * 8 + r) * WSL + kw + q;
            const uint32_t* bl = (const uint32_t*)s_wl + (nwb + nt * 8 + r) * WSL + kw + q;
            uint32_t bh0 = bh[0], bh1 = bh[4], bl0 = bl[0], bl1 = bl[4];
            #pragma unroll
            for (int mt = 0; mt < 4; mt++) {
                MMA_F16(acc[mt][nt], ah[mt], bh0, bh1);
                MMA_F16(acc[mt][nt], ah[mt], bl0, bl1);
                MMA_F16(acc[mt][nt], al[mt], bh0, bh1);
            }
        }
    }
    #pragma unroll
    for (int mt = 0; mt < 4; mt++)
        #pragma unroll
        for (int nt = 0; nt < NT; nt++)
            #pragma unroll
            for (int rr = 0; rr < 2; rr++) {
                int node = base + mrow + mt * 16 + r + 8 * rr;
                if (node < N) {
                    int c0 = nwb + nt * 8 + 2 * q;
                    float2 v;
                    v.x = fmaxf(acc[mt][nt][2 * rr + 0], 0.f);
                    v.y = fmaxf(acc[mt][nt][2 * rr + 1], 0.f);
                    *(float2*)(outp + (size_t)node * KOUT + c0) = v;
                }
            }
}

// ---------------- host launcher ----------------
static void* symaddr(const void* sym) {
    void* p = nullptr;
    cudaGetSymbolAddress(&p, sym);
    return p;
}

extern "C" void kernel_launch(void* const* d_in, const int* in_sizes, int n_in,
                              void* d_out, int out_size) {
    const float* x   = (const float*)d_in[0];
    const int*   ei  = (const int*)d_in[1];
    const int N = in_sizes[0] / 64;
    const int E = in_sizes[1] / 2;
    const int* src = ei;

    const float* p1pw  = (const float*)d_in[3];
    const float* p1pb  = (const float*)d_in[4];
    const float* p1wih = (const float*)d_in[5];
    const float* p1whh = (const float*)d_in[6];
    const float* p1bih = (const float*)d_in[7];
    const float* p1bhh = (const float*)d_in[8];
    const float* p1llw = (const float*)d_in[9];
    const float* p1llb = (const float*)d_in[10];
    const float* p1lrw = (const float*)d_in[11];
    const float* p2pw  = (const float*)d_in[12];
    const float* p2pb  = (const float*)d_in[13];
    const float* p2wih = (const float*)d_in[14];
    const float* p2whh = (const float*)d_in[15];
    const float* p2bih = (const float*)d_in[16];
    const float* p2bhh = (const float*)d_in[17];
    const float* p2llw = (const float*)d_in[18];
    const float* p2llb = (const float*)d_in[19];
    const float* p2lrw = (const float*)d_in[20];
    const float* l1w   = (const float*)d_in[21];
    const float* l1b   = (const float*)d_in[22];
    const float* l2w   = (const float*)d_in[23];
    const float* l2b   = (const float*)d_in[24];
    const float* l3w   = (const float*)d_in[25];
    const float* l3b   = (const float*)d_in[26];

    __half* xg  = (__half*)symaddr(g_xg);
    float*  hb  = (float*)symaddr(g_hb);
    float*  h1  = (float*)symaddr(g_h1);
    float*  h2  = (float*)symaddr(g_h2);
    float*  t1  = (float*)symaddr(g_t1);
    float*  t2  = (float*)symaddr(g_t2);
    __half* wx1 = (__half*)symaddr(g_wx1);
    __half* wh1 = (__half*)symaddr(g_wh1);
    __half* wx2 = (__half*)symaddr(g_wx2);
    __half* wh2 = (__half*)symaddr(g_wh2);
    float*  bs1 = (float*)symaddr(g_bs1);
    float*  bs2 = (float*)symaddr(g_bs2);
    __half* wo1h = (__half*)symaddr(g_wo1h); __half* wo1l = (__half*)symaddr(g_wo1l);
    __half* wo2h = (__half*)symaddr(g_wo2h); __half* wo2l = (__half*)symaddr(g_wo2l);
    __half* pT1h = (__half*)symaddr(g_pT1h); __half* pT1l = (__half*)symaddr(g_pT1l);
    __half* pT2h = (__half*)symaddr(g_pT2h); __half* pT2l = (__half*)symaddr(g_pT2l);
    __half* l1h  = (__half*)symaddr(g_l1h);  __half* l1l  = (__half*)symaddr(g_l1l);
    __half* l2h  = (__half*)symaddr(g_l2h);  __half* l2l  = (__half*)symaddr(g_l2l);
    __half* l3h  = (__half*)symaddr(g_l3h);  __half* l3l  = (__half*)symaddr(g_l3l);

    // smem sizes
    const int SM_REC  = 23040 * 2 + 512 * 4;                                     // 48128
    const int SM_XPG  = 36864 * 2 + 320 * 4;                                     // 75008
    const int SM_SAGE64  = (2 * 64 * KH128 + 2 * 128 * KH128) * 2 + 64 * 4;      // 104704
    const int SM_SAGE128 = (2 * 128 * KH128 + 2 * 128 * KH128) * 2 + 128 * 4;    // 139776
    const int SM_6464 = (2 * 64 * 72 + 2 * 128 * 72) * 2 + 64 * 4;               // 55552
    const int SM_L1   = (2 * 192 * 136 + 2 * 128 * 136) * 2 + 192 * 4;           // 174848
    const int SM_L2   = (2 * 64 * 200 + 2 * 128 * 200) * 2 + 64 * 4;             // 153856
    cudaFuncSetAttribute(lstm_rec,            cudaFuncAttributeMaxDynamicSharedMemorySize, SM_REC);
    cudaFuncSetAttribute(xpg_kernel,          cudaFuncAttributeMaxDynamicSharedMemorySize, SM_XPG);
    cudaFuncSetAttribute(sage_linear<64>,     cudaFuncAttributeMaxDynamicSharedMemorySize, SM_SAGE64);
    cudaFuncSetAttribute(sage_linear<128>,    cudaFuncAttributeMaxDynamicSharedMemorySize, SM_SAGE128);
    cudaFuncSetAttribute(mma_linear<128, 192>, cudaFuncAttributeMaxDynamicSharedMemorySize, SM_L1);
    cudaFuncSetAttribute(mma_linear<192, 64>, cudaFuncAttributeMaxDynamicSharedMemorySize, SM_L2);
    cudaFuncSetAttribute(mma_linear<64, 64>,  cudaFuncAttributeMaxDynamicSharedMemorySize, SM_6464);

    // --- fused weight prep ---
    k_prep_all<<<544, 256>>>(p1wih, p1whh, p1bih, p1bhh,
                             p2wih, p2whh, p2bih, p2bhh,
                             p1llw, p1lrw, p2llw, p2lrw,
                             p1pw, p2pw, l1w, l2w, l3w);

    const int NB128 = (N + 127) / 128;
    const int NB64  = (N + 63) / 64;
    const int NB32  = (N + 31) / 32;

    // --- layer 1 ---
    xpg_kernel<<<NB64, 256, SM_XPG>>>(x, pT1h, pT1l, p1pb, wx1, bs1, xg, N);
    lstm_rec<<<NB32, 128, SM_REC>>>(xg, src, wh1, hb, N);
    sage_linear<64><<<NB128, 256, SM_SAGE64>>>(x, hb, wo1h, wo1l, p1llb, h1, N);
    // --- layer 2 ---
    xpg_kernel<<<NB64, 256, SM_XPG>>>(h1, pT2h, pT2l, p2pb, wx2, bs2, xg, N);
    lstm_rec<<<NB32, 128, SM_REC>>>(xg, src, wh2, hb, N);
    sage_linear<128><<<NB128, 256, SM_SAGE128>>>(h1, hb, wo2h, wo2l, p2llb, h2, N);
    // --- MLP head ---
    mma_linear<128, 192><<<NB128, 256, SM_L1>>>(h2, l1h, l1l, l1b, t1, N);
    mma_linear<192, 64><<<NB128, 256, SM_L2>>>(t1, l2h, l2l, l2b, t2, N);
    mma_linear<64, 64><<<NB128, 256, SM_6464>>>(t2, l3h, l3l, l3b, (float*)d_out, N);

    // --- edge_index passthrough if the output buffer holds it ---
    long hsz = (long)N * 64;
    if ((long)out_size > hsz) {
        long remaining = (long)out_size - hsz;
        int count = (int)((remaining < (long)2 * E) ? remaining : (long)2 * E);
        k_edge_copy<<<(count + 255) / 256, 256>>>(ei, (float*)d_out + hsz, count);
    }
}